// round 9
// baseline (speedup 1.0000x reference)
#include <cuda_runtime.h>
#include <cuda_fp16.h>
#include <cstdint>

#define BB      8
#define NODES   1600
#define VD      256
#define FD      256
#define MTOT    (BB * NODES)   // 12800
#define KCH     32
#define NCH     (NODES / KCH)  // 50  (k_mma2f)
#define NCHG    (VD / KCH)     // 8   (k_g1mma)
// k_g1mma stages (A hi/lo + B hi/lo)
#define STAGE_G 30720
#define SMEM_G  (2 * STAGE_G)
// k_mma2f smem layout (bytes from base):
//   Wh2s 6400 | wh1s 256 | ms 256 | bm 12800 | A0 5120 | A1 5120 | B0 20480 | B1 20480
#define ABASE   19712
#define BBASE   (ABASE + 2 * 5120)      // 29952
#define SMEM_M  (BBASE + 2 * 20480)     // 70912

// ---------------- scratch (device globals; allocation-free) ----------------
__device__ float                 g_Wh1 [MTOT];
__device__ float                 g_Wh2 [MTOT];
__device__ float                 g_ui[VD], g_uj[VD];
__device__ float                 g_ci, g_cj;
__device__ uint32_t              g_bm[NODES * 50];
__device__ __align__(128) __half g_xh[(size_t)MTOT * VD];
__device__ __align__(128) __half g_xl[(size_t)MTOT * VD];
__device__ __align__(128) __half g_W16h[FD * VD];
__device__ __align__(128) __half g_W16l[FD * VD];
__device__ __align__(128) __half g_WhT_hi[BB * FD * NODES];
__device__ __align__(128) __half g_WhT_lo[BB * FD * NODES];

// ---------------- PTX helpers (sm_80-era only) ----------------
__device__ __forceinline__ uint32_t smem_u32(const void* p) {
    uint32_t a;
    asm("{ .reg .u64 t; cvta.to.shared.u64 t, %1; cvt.u32.u64 %0, t; }" : "=r"(a) : "l"(p));
    return a;
}
__device__ __forceinline__ void cp16(uint32_t dst, const void* src) {
    asm volatile("cp.async.cg.shared.global [%0], [%1], 16;" :: "r"(dst), "l"(src) : "memory");
}
#define CP_COMMIT() asm volatile("cp.async.commit_group;" ::: "memory")
#define CP_WAIT1()  asm volatile("cp.async.wait_group 1;" ::: "memory")
#define CP_WAIT0()  asm volatile("cp.async.wait_group 0;" ::: "memory")

__device__ __forceinline__ void ldmx4(uint32_t* r, uint32_t addr) {
    asm volatile("ldmatrix.sync.aligned.m8n8.x4.shared.b16 {%0,%1,%2,%3}, [%4];"
                 : "=r"(r[0]), "=r"(r[1]), "=r"(r[2]), "=r"(r[3]) : "r"(addr));
}
__device__ __forceinline__ void mma16816(float* c, const uint32_t* a,
                                         uint32_t b0, uint32_t b1) {
    asm volatile(
        "mma.sync.aligned.m16n8k16.row.col.f32.f16.f16.f32 "
        "{%0,%1,%2,%3}, {%4,%5,%6,%7}, {%8,%9}, {%0,%1,%2,%3};"
        : "+f"(c[0]), "+f"(c[1]), "+f"(c[2]), "+f"(c[3])
        : "r"(a[0]), "r"(a[1]), "r"(a[2]), "r"(a[3]), "r"(b0), "r"(b1));
}
__device__ __forceinline__ void split2(float v0, float v1, __half2& h, __half2& l) {
    __half h0 = __float2half_rn(v0), h1 = __float2half_rn(v1);
    h = __halves2half2(h0, h1);
    l = __halves2half2(__float2half_rn(v0 - __half2float(h0)),
                       __float2half_rn(v1 - __half2float(h1)));
}

// ---------------------------------------------------------------------------
// k_split_x: x fp32 -> xh/xl fp16 split
// ---------------------------------------------------------------------------
__global__ __launch_bounds__(256) void k_split_x(const float4* __restrict__ x) {
    const size_t idx = (size_t)blockIdx.x * 256 + threadIdx.x;
    float4 v = x[idx];
    __half2 h01, l01, h23, l23;
    split2(v.x, v.y, h01, l01);
    split2(v.z, v.w, h23, l23);
    __half2* ph = (__half2*)&g_xh[idx * 4];
    __half2* pl = (__half2*)&g_xl[idx * 4];
    ph[0] = h01; ph[1] = h23;
    pl[0] = l01; pl[1] = l23;
}

// ---------------------------------------------------------------------------
// k_wprep: u_i = W^T ai, u_j = W^T aj, c_i/c_j; W -> fp16 split. One CTA.
// ---------------------------------------------------------------------------
__global__ __launch_bounds__(256) void k_wprep(const float* __restrict__ W,
                                               const float* __restrict__ bW,
                                               const float* __restrict__ ai,
                                               const float* __restrict__ bi,
                                               const float* __restrict__ aj,
                                               const float* __restrict__ bj) {
    __shared__ float red[16];
    const int v = threadIdx.x;
    float ui = 0.f, uj = 0.f;
    for (int f = 0; f < FD; f++) {
        float w = W[f * VD + v];
        ui += ai[f] * w;
        uj += aj[f] * w;
    }
    g_ui[v] = ui;
    g_uj[v] = uj;

    for (int t = v; t < FD * VD / 2; t += 256) {
        float2 w2 = ((const float2*)W)[t];
        __half2 h, l;
        split2(w2.x, w2.y, h, l);
        *(__half2*)&g_W16h[2 * t] = h;
        *(__half2*)&g_W16l[2 * t] = l;
    }

    float p1 = ai[v] * bW[v];
    float p2 = aj[v] * bW[v];
    const int warp = v >> 5, lane = v & 31;
#pragma unroll
    for (int o = 16; o; o >>= 1) {
        p1 += __shfl_xor_sync(0xFFFFFFFFu, p1, o);
        p2 += __shfl_xor_sync(0xFFFFFFFFu, p2, o);
    }
    if (lane == 0) { red[warp] = p1; red[8 + warp] = p2; }
    __syncthreads();
    if (v == 0) {
        float c1 = bi[0], c2 = bj[0];
        for (int w = 0; w < 8; w++) { c1 += red[w]; c2 += red[8 + w]; }
        g_ci = c1; g_cj = c2;
    }
}

// ---------------------------------------------------------------------------
// k_projx: Wh1/Wh2 directly from x (warp per row)
// ---------------------------------------------------------------------------
__global__ __launch_bounds__(256) void k_projx(const float* __restrict__ x) {
    const int gwarp = (blockIdx.x * blockDim.x + threadIdx.x) >> 5;
    const int lane = threadIdx.x & 31;
    const float* row = x + (size_t)gwarp * VD;
    float s1 = 0.f, s2 = 0.f;
#pragma unroll
    for (int q = 0; q < 8; q++) {
        const int k = lane + 32 * q;
        float v = row[k];
        s1 += v * g_ui[k];
        s2 += v * g_uj[k];
    }
#pragma unroll
    for (int o = 16; o; o >>= 1) {
        s1 += __shfl_xor_sync(0xFFFFFFFFu, s1, o);
        s2 += __shfl_xor_sync(0xFFFFFFFFu, s2, o);
    }
    if (lane == 0) {
        g_Wh1[gwarp] = s1 + g_ci;
        g_Wh2[gwarp] = s2 + g_cj;
    }
}

// ---------------------------------------------------------------------------
// k_bm: adjacency -> bitmask (once; batch-independent). Warp per row.
// ---------------------------------------------------------------------------
__global__ __launch_bounds__(256) void k_bm(const int* __restrict__ adj) {
    const int row = blockIdx.x * 8 + (threadIdx.x >> 5);
    const int lane = threadIdx.x & 31;
    const int* ar = adj + (size_t)row * NODES;
    for (int w = 0; w < 50; w++) {
        uint32_t bit = __ballot_sync(0xFFFFFFFFu, ar[w * 32 + lane] > 0);
        if (lane == 0) g_bm[row * 50 + w] = bit;
    }
}

// ---------------------------------------------------------------------------
// k_g1mma: Wh = x @ W^T (+bW), 3-term fp16 hi/lo; epilogue -> WhT hi/lo.
// ---------------------------------------------------------------------------
__global__ __launch_bounds__(256) void k_g1mma(const float* __restrict__ bW) {
    extern __shared__ __align__(128) char dsm[];
    __shared__ float bWs[128];
    const int tid = threadIdx.x, wid = tid >> 5, lane = tid & 31;
    const int m0 = blockIdx.x * 64, n0 = blockIdx.y * 128;
    const int wm = wid >> 2, wn = wid & 3;

    if (tid < 128) bWs[tid] = bW[n0 + tid];

    const __half* Ah = g_xh + (size_t)m0 * VD;
    const __half* Al = g_xl + (size_t)m0 * VD;
    const __half* Bh = g_W16h + (size_t)n0 * VD;
    const __half* Bl = g_W16l + (size_t)n0 * VD;

    const uint32_t s0 = smem_u32(dsm);

    auto load_chunk = [&](int c) {
        const uint32_t st = s0 + (c & 1) * STAGE_G;
        const int jt = c * KCH;
        {
            int row = tid >> 2, cc = tid & 3;
            uint32_t o = (uint32_t)(row * 80 + cc * 16);
            const size_t go = (size_t)row * VD + jt + cc * 8;
            cp16(st + o,        Ah + go);
            cp16(st + 5120 + o, Al + go);
        }
        for (int t = tid; t < 512; t += 256) {
            int row = t >> 2, cc = t & 3;
            uint32_t o = (uint32_t)(row * 80 + cc * 16);
            const size_t go = (size_t)row * VD + jt + cc * 8;
            cp16(st + 10240 + o, Bh + go);
            cp16(st + 20480 + o, Bl + go);
        }
        CP_COMMIT();
    };

    float acc[2][4][4];
#pragma unroll
    for (int mt = 0; mt < 2; mt++)
#pragma unroll
        for (int nt = 0; nt < 4; nt++)
#pragma unroll
            for (int q = 0; q < 4; q++) acc[mt][nt][q] = 0.f;

    const int aRow = wm * 32 + (lane & 7) + ((lane >> 3) & 1) * 8;
    const int aC16 = ((lane >> 4) & 1) * 16;
    const int bRow = wn * 32 + (lane & 7) + ((lane >> 4) & 1) * 8;
    const int bC16 = ((lane >> 3) & 1) * 16;

    load_chunk(0);

    for (int c = 0; c < NCHG; c++) {
        if (c + 1 < NCHG) { load_chunk(c + 1); CP_WAIT1(); }
        else             { CP_WAIT0(); }
        __syncthreads();
        const uint32_t st = s0 + (c & 1) * STAGE_G;
#pragma unroll
        for (int ks = 0; ks < 2; ks++) {
            const int koff = ks * 32;
            uint32_t ah[2][4], al[2][4], bh[2][4], bl[2][4];
#pragma unroll
            for (int mt = 0; mt < 2; mt++) {
                uint32_t ao = st + (uint32_t)((aRow + mt * 16) * 80 + aC16 + koff);
                ldmx4(ah[mt], ao);
                ldmx4(al[mt], ao + 5120);
            }
#pragma unroll
            for (int p = 0; p < 2; p++) {
                uint32_t bo = st + 10240 +
                              (uint32_t)((bRow + p * 16) * 80 + bC16 + koff);
                ldmx4(bh[p], bo);
                ldmx4(bl[p], bo + 10240);
            }
#pragma unroll
            for (int mt = 0; mt < 2; mt++) {
#pragma unroll
                for (int nt = 0; nt < 4; nt++) {
                    const int p = nt >> 1, hf = (nt & 1) * 2;
                    mma16816(acc[mt][nt], ah[mt], bh[p][hf], bh[p][hf + 1]);
                    mma16816(acc[mt][nt], ah[mt], bl[p][hf], bl[p][hf + 1]);
                    mma16816(acc[mt][nt], al[mt], bh[p][hf], bh[p][hf + 1]);
                }
            }
        }
        __syncthreads();
    }

    float* s = (float*)dsm;   // [64][129]
#pragma unroll
    for (int mt = 0; mt < 2; mt++) {
        const int ml = wm * 32 + mt * 16 + (lane >> 2);
#pragma unroll
        for (int nt = 0; nt < 4; nt++) {
            const int nl = wn * 32 + nt * 8 + (lane & 3) * 2;
            s[ml * 129 + nl]           = acc[mt][nt][0];
            s[ml * 129 + nl + 1]       = acc[mt][nt][1];
            s[(ml + 8) * 129 + nl]     = acc[mt][nt][2];
            s[(ml + 8) * 129 + nl + 1] = acc[mt][nt][3];
        }
    }
    __syncthreads();

    const int b  = m0 / NODES;
    const int j0 = m0 % NODES;
#pragma unroll
    for (int it = 0; it < 16; it++) {
        const int f = wid * 16 + it;
        const float bw = bWs[f];
        float v0 = s[(2 * lane) * 129 + f] + bw;
        float v1 = s[(2 * lane + 1) * 129 + f] + bw;
        __half2 h, l;
        split2(v0, v1, h, l);
        size_t o = ((size_t)(b * FD + n0 + f)) * NODES + j0 + 2 * lane;
        *(__half2*)&g_WhT_hi[o] = h;
        *(__half2*)&g_WhT_lo[o] = l;
    }
}

// ---------------------------------------------------------------------------
// k_mma2f: FUSED masked-softmax + P @ Wh^T + deferred norm + ELU.
// Software-pipelined: P(c+1) computed UNDER the MMAs of chunk c; 1 sync/chunk.
// ---------------------------------------------------------------------------
__global__ __launch_bounds__(256) void k_mma2f(float* __restrict__ out) {
    extern __shared__ __align__(128) char dsm[];
    float*    Wh2s = (float*)dsm;                 // 1600
    float*    wh1s = Wh2s + NODES;                // 64
    float*    ms   = wh1s + 64;                   // 64
    uint32_t* bms  = (uint32_t*)(ms + 64);        // 64*50

    const int tid = threadIdx.x, wid = tid >> 5, lane = tid & 31;
    const int m0 = blockIdx.x * 64, n0 = blockIdx.y * 128, b = blockIdx.z;
    const int wm = wid >> 2, wn = wid & 3;

    const __half* Bh = g_WhT_hi + ((size_t)b * FD + n0) * NODES;
    const __half* Bl = g_WhT_lo + ((size_t)b * FD + n0) * NODES;

    const uint32_t s0 = smem_u32(dsm);
    const uint32_t sA = s0 + ABASE;
    const uint32_t sB = s0 + BBASE;

    auto loadB = [&](int c) {
        const uint32_t st = sB + (c & 1) * 20480;
        const int jt = c * KCH;
        for (int t = tid; t < 512; t += 256) {
            int row = t >> 2, cc = t & 3;
            uint32_t o = (uint32_t)(row * 80 + cc * 16);
            const size_t go = (size_t)row * NODES + jt + cc * 8;
            cp16(st + o,         Bh + go);
            cp16(st + 10240 + o, Bl + go);
        }
        CP_COMMIT();
    };

    loadB(0);

    // ---- fill smem: Wh2 row, Wh1 tile, bitmask rows ----
    for (int j = tid; j < NODES; j += 256)
        Wh2s[j] = g_Wh2[b * NODES + j];
    if (tid < 64)
        wh1s[tid] = g_Wh1[b * NODES + m0 + tid];
    for (int t = tid; t < 64 * 50; t += 256)
        bms[t] = g_bm[m0 * 50 + t];
    __syncthreads();

    // ---- prologue: masked max per row (warp wid -> rows wid*8..wid*8+7) ----
#pragma unroll
    for (int rr = 0; rr < 8; rr++) {
        const int r = wid * 8 + rr;
        const uint32_t* bmr = &bms[r * 50];
        float mx = -3e38f;
        for (int w = 0; w < 50; w++)
            if ((bmr[w] >> lane) & 1) mx = fmaxf(mx, Wh2s[w * 32 + lane]);
#pragma unroll
        for (int o = 16; o; o >>= 1) mx = fmaxf(mx, __shfl_xor_sync(0xFFFFFFFFu, mx, o));
        if (lane == 0) {
            float em = wh1s[r] + mx;
            em = em > 0.f ? em : 0.2f * em;
            ms[r] = (mx > -1e30f) ? em : -1e9f;
        }
    }
    __syncthreads();

    float acc[2][4][4];
    float accs[2][4];
#pragma unroll
    for (int mt = 0; mt < 2; mt++) {
#pragma unroll
        for (int nt = 0; nt < 4; nt++)
#pragma unroll
            for (int q = 0; q < 4; q++) acc[mt][nt][q] = 0.f;
#pragma unroll
        for (int q = 0; q < 4; q++) accs[mt][q] = 0.f;
    }

    const int aRow = wm * 32 + (lane & 7) + ((lane >> 3) & 1) * 8;
    const int aC16 = ((lane >> 4) & 1) * 16;
    const int bRow = wn * 32 + (lane & 7) + ((lane >> 4) & 1) * 8;
    const int bC16 = ((lane >> 3) & 1) * 16;
    const uint32_t ONES2 = 0x3C003C00u;  // half2(1.0, 1.0)

    // P-tile compute mapping: thread -> row pr (0..63), col group pq (0..3)
    const int pr = tid >> 2, pq = tid & 3;
    const float wh1r = wh1s[pr];
    const float mr   = ms[pr];
    const uint32_t* bmp = &bms[pr * 50];

    // P(c) tile -> A buffer (c&1)
    auto computeA = [&](int c) {
        const int jt = c * KCH;
        const uint32_t word = bmp[c];          // KCH == 32: one word per chunk
        uint32_t uv[4];
#pragma unroll
        for (int u = 0; u < 4; u++) {
            const int jj = pq * 8 + u * 2;
            float2 w2 = *(const float2*)&Wh2s[jt + jj];
            float e0 = wh1r + w2.x; e0 = e0 > 0.f ? e0 : 0.2f * e0;
            float e1 = wh1r + w2.y; e1 = e1 > 0.f ? e1 : 0.2f * e1;
            float x0 = ((word >> jj) & 1)       ? __expf(e0 - mr) : 0.f;
            float x1 = ((word >> (jj + 1)) & 1) ? __expf(e1 - mr) : 0.f;
            __half2 hh = __halves2half2(__float2half_rn(x0), __float2half_rn(x1));
            uv[u] = *(uint32_t*)&hh;
        }
        *(uint4*)(dsm + ABASE + (c & 1) * 5120 + pr * 80 + pq * 16) =
            make_uint4(uv[0], uv[1], uv[2], uv[3]);
    };

    computeA(0);   // A(0); visible after first loop sync

    for (int c = 0; c < NCH; c++) {
        CP_WAIT0();          // B(c) resident (only group c in flight here)
        __syncthreads();     // X(c): A(c)+B(c) visible; chunk c-1 smem reads done

        if (c + 1 < NCH) loadB(c + 1);   // safe: buf (c+1)&1 readers done pre-X(c)

        const uint32_t stA = sA + (c & 1) * 5120;
        const uint32_t stB = sB + (c & 1) * 20480;
#pragma unroll
        for (int ks = 0; ks < 2; ks++) {
            const int koff = ks * 32;
            uint32_t ah[2][4], bh[2][4], bl[2][4];
#pragma unroll
            for (int mt = 0; mt < 2; mt++) {
                uint32_t ao = stA + (uint32_t)((aRow + mt * 16) * 80 + aC16 + koff);
                ldmx4(ah[mt], ao);
            }
#pragma unroll
            for (int p = 0; p < 2; p++) {
                uint32_t bo = stB + (uint32_t)((bRow + p * 16) * 80 + bC16 + koff);
                ldmx4(bh[p], bo);
                ldmx4(bl[p], bo + 10240);
            }
#pragma unroll
            for (int mt = 0; mt < 2; mt++) {
#pragma unroll
                for (int nt = 0; nt < 4; nt++) {
                    const int p = nt >> 1, hf = (nt & 1) * 2;
                    mma16816(acc[mt][nt], ah[mt], bh[p][hf], bh[p][hf + 1]);
                    mma16816(acc[mt][nt], ah[mt], bl[p][hf], bl[p][hf + 1]);
                }
                mma16816(accs[mt], ah[mt], ONES2, ONES2);  // row sums
            }
        }

        // overlap: P(c+1) issues while chunk-c HMMAs drain on the tensor pipe
        if (c + 1 < NCH) computeA(c + 1);
    }

    // ---- epilogue: scale by 1/rowsum, ELU, store ----
#pragma unroll
    for (int mt = 0; mt < 2; mt++) {
        const int mA = m0 + wm * 32 + mt * 16 + (lane >> 2);
        const float ilA = 1.f / accs[mt][0];
        const float ilB = 1.f / accs[mt][2];
#pragma unroll
        for (int nt = 0; nt < 4; nt++) {
            const int n = n0 + wn * 32 + nt * 8 + (lane & 3) * 2;
            float* op = out + ((size_t)(b * NODES) + mA) * FD + n;
            float d0 = acc[mt][nt][0] * ilA, d1 = acc[mt][nt][1] * ilA;
            float d2 = acc[mt][nt][2] * ilB, d3 = acc[mt][nt][3] * ilB;
            float2 v0, v1;
            v0.x = d0 > 0.f ? d0 : (__expf(d0) - 1.f);
            v0.y = d1 > 0.f ? d1 : (__expf(d1) - 1.f);
            v1.x = d2 > 0.f ? d2 : (__expf(d2) - 1.f);
            v1.y = d3 > 0.f ? d3 : (__expf(d3) - 1.f);
            *(float2*)op = v0;
            *(float2*)(op + 8 * FD) = v1;
        }
    }
}

// ---------------------------------------------------------------------------
extern "C" void kernel_launch(void* const* d_in, const int* in_sizes, int n_in,
                              void* d_out, int out_size) {
    const float* h   = (const float*)d_in[0];
    const int*   adj = (const int*)  d_in[1];
    const float* W   = (const float*)d_in[2];
    const float* bW  = (const float*)d_in[3];
    const float* ai  = (const float*)d_in[4];
    const float* bi  = (const float*)d_in[5];
    const float* aj  = (const float*)d_in[6];
    const float* bj  = (const float*)d_in[7];
    float* out = (float*)d_out;

    cudaFuncSetAttribute(k_g1mma, cudaFuncAttributeMaxDynamicSharedMemorySize, SMEM_G);
    cudaFuncSetAttribute(k_mma2f, cudaFuncAttributeMaxDynamicSharedMemorySize, SMEM_M);

    k_split_x<<<(MTOT * VD / 4) / 256, 256>>>((const float4*)h);
    k_wprep<<<1, 256>>>(W, bW, ai, bi, aj, bj);
    k_projx<<<MTOT / 8, 256>>>(h);
    k_bm<<<NODES / 8, 256>>>(adj);
    k_g1mma<<<dim3(MTOT / 64, 2), 256, SMEM_G>>>(bW);
    dim3 gm(NODES / 64, FD / 128, BB);
    k_mma2f<<<gm, 256, SMEM_M>>>(out);
}

// round 10
// speedup vs baseline: 1.1181x; 1.1181x over previous
#include <cuda_runtime.h>
#include <cuda_fp16.h>
#include <cstdint>

#define BB      8
#define NODES   1600
#define VD      256
#define FD      256
#define MTOT    (BB * NODES)   // 12800
#define KCH     32
#define NCH     (NODES / KCH)  // 50  (k_mma2f)
#define NCHG    (VD / KCH)     // 8   (k_g1mma)
// k_g1mma stages (A hi/lo + B hi/lo)
#define STAGE_G 30720
#define SMEM_G  (2 * STAGE_G)
// k_mma2f smem layout (bytes from base):
//   Wh2s 6400 | wh1s 256 | ms 256 | bm 12800 | A0 5120 | A1 5120 | B0 20480 | B1 20480
#define ABASE   19712
#define BBASE   (ABASE + 2 * 5120)      // 29952
#define SMEM_M  (BBASE + 2 * 20480)     // 70912

// ---------------- scratch (device globals; allocation-free) ----------------
__device__ float                 g_Wh1 [MTOT];
__device__ float                 g_Wh2 [MTOT];
__device__ float                 g_ui[VD], g_uj[VD];
__device__ float                 g_ci, g_cj;
__device__ uint32_t              g_bm[NODES * 50];
__device__ __align__(128) __half g_xh[(size_t)MTOT * VD];
__device__ __align__(128) __half g_xl[(size_t)MTOT * VD];
__device__ __align__(128) __half g_W16h[FD * VD];
__device__ __align__(128) __half g_W16l[FD * VD];
__device__ __align__(128) __half g_WhT_hi[BB * FD * NODES];
__device__ __align__(128) __half g_WhT_lo[BB * FD * NODES];

// ---------------- PTX helpers (sm_80-era only) ----------------
__device__ __forceinline__ uint32_t smem_u32(const void* p) {
    uint32_t a;
    asm("{ .reg .u64 t; cvta.to.shared.u64 t, %1; cvt.u32.u64 %0, t; }" : "=r"(a) : "l"(p));
    return a;
}
__device__ __forceinline__ void cp16(uint32_t dst, const void* src) {
    asm volatile("cp.async.cg.shared.global [%0], [%1], 16;" :: "r"(dst), "l"(src) : "memory");
}
#define CP_COMMIT() asm volatile("cp.async.commit_group;" ::: "memory")
#define CP_WAIT1()  asm volatile("cp.async.wait_group 1;" ::: "memory")
#define CP_WAIT0()  asm volatile("cp.async.wait_group 0;" ::: "memory")

__device__ __forceinline__ void ldmx4(uint32_t* r, uint32_t addr) {
    asm volatile("ldmatrix.sync.aligned.m8n8.x4.shared.b16 {%0,%1,%2,%3}, [%4];"
                 : "=r"(r[0]), "=r"(r[1]), "=r"(r[2]), "=r"(r[3]) : "r"(addr));
}
__device__ __forceinline__ void mma16816(float* c, const uint32_t* a,
                                         uint32_t b0, uint32_t b1) {
    asm volatile(
        "mma.sync.aligned.m16n8k16.row.col.f32.f16.f16.f32 "
        "{%0,%1,%2,%3}, {%4,%5,%6,%7}, {%8,%9}, {%0,%1,%2,%3};"
        : "+f"(c[0]), "+f"(c[1]), "+f"(c[2]), "+f"(c[3])
        : "r"(a[0]), "r"(a[1]), "r"(a[2]), "r"(a[3]), "r"(b0), "r"(b1));
}
__device__ __forceinline__ void split2(float v0, float v1, __half2& h, __half2& l) {
    __half h0 = __float2half_rn(v0), h1 = __float2half_rn(v1);
    h = __halves2half2(h0, h1);
    l = __halves2half2(__float2half_rn(v0 - __half2float(h0)),
                       __float2half_rn(v1 - __half2float(h1)));
}

// ---------------------------------------------------------------------------
// k_split_x: x fp32 -> xh/xl fp16 split
// ---------------------------------------------------------------------------
__global__ __launch_bounds__(256) void k_split_x(const float4* __restrict__ x) {
    const size_t idx = (size_t)blockIdx.x * 256 + threadIdx.x;
    float4 v = x[idx];
    __half2 h01, l01, h23, l23;
    split2(v.x, v.y, h01, l01);
    split2(v.z, v.w, h23, l23);
    __half2* ph = (__half2*)&g_xh[idx * 4];
    __half2* pl = (__half2*)&g_xl[idx * 4];
    ph[0] = h01; ph[1] = h23;
    pl[0] = l01; pl[1] = l23;
}

// ---------------------------------------------------------------------------
// k_wprep: u_i = W^T ai, u_j = W^T aj, c_i/c_j; W -> fp16 split. One CTA.
// ---------------------------------------------------------------------------
__global__ __launch_bounds__(256) void k_wprep(const float* __restrict__ W,
                                               const float* __restrict__ bW,
                                               const float* __restrict__ ai,
                                               const float* __restrict__ bi,
                                               const float* __restrict__ aj,
                                               const float* __restrict__ bj) {
    __shared__ float red[16];
    const int v = threadIdx.x;
    float ui = 0.f, uj = 0.f;
    for (int f = 0; f < FD; f++) {
        float w = W[f * VD + v];
        ui += ai[f] * w;
        uj += aj[f] * w;
    }
    g_ui[v] = ui;
    g_uj[v] = uj;

    for (int t = v; t < FD * VD / 2; t += 256) {
        float2 w2 = ((const float2*)W)[t];
        __half2 h, l;
        split2(w2.x, w2.y, h, l);
        *(__half2*)&g_W16h[2 * t] = h;
        *(__half2*)&g_W16l[2 * t] = l;
    }

    float p1 = ai[v] * bW[v];
    float p2 = aj[v] * bW[v];
    const int warp = v >> 5, lane = v & 31;
#pragma unroll
    for (int o = 16; o; o >>= 1) {
        p1 += __shfl_xor_sync(0xFFFFFFFFu, p1, o);
        p2 += __shfl_xor_sync(0xFFFFFFFFu, p2, o);
    }
    if (lane == 0) { red[warp] = p1; red[8 + warp] = p2; }
    __syncthreads();
    if (v == 0) {
        float c1 = bi[0], c2 = bj[0];
        for (int w = 0; w < 8; w++) { c1 += red[w]; c2 += red[8 + w]; }
        g_ci = c1; g_cj = c2;
    }
}

// ---------------------------------------------------------------------------
// k_projx: Wh1/Wh2 directly from x (warp per row)
// ---------------------------------------------------------------------------
__global__ __launch_bounds__(256) void k_projx(const float* __restrict__ x) {
    const int gwarp = (blockIdx.x * blockDim.x + threadIdx.x) >> 5;
    const int lane = threadIdx.x & 31;
    const float* row = x + (size_t)gwarp * VD;
    float s1 = 0.f, s2 = 0.f;
#pragma unroll
    for (int q = 0; q < 8; q++) {
        const int k = lane + 32 * q;
        float v = row[k];
        s1 += v * g_ui[k];
        s2 += v * g_uj[k];
    }
#pragma unroll
    for (int o = 16; o; o >>= 1) {
        s1 += __shfl_xor_sync(0xFFFFFFFFu, s1, o);
        s2 += __shfl_xor_sync(0xFFFFFFFFu, s2, o);
    }
    if (lane == 0) {
        g_Wh1[gwarp] = s1 + g_ci;
        g_Wh2[gwarp] = s2 + g_cj;
    }
}

// ---------------------------------------------------------------------------
// k_bm: adjacency -> bitmask (once; batch-independent). Warp per row.
// ---------------------------------------------------------------------------
__global__ __launch_bounds__(256) void k_bm(const int* __restrict__ adj) {
    const int row = blockIdx.x * 8 + (threadIdx.x >> 5);
    const int lane = threadIdx.x & 31;
    const int* ar = adj + (size_t)row * NODES;
    for (int w = 0; w < 50; w++) {
        uint32_t bit = __ballot_sync(0xFFFFFFFFu, ar[w * 32 + lane] > 0);
        if (lane == 0) g_bm[row * 50 + w] = bit;
    }
}

// ---------------------------------------------------------------------------
// k_g1mma: Wh = x @ W^T (+bW), 3-term fp16 hi/lo; epilogue -> WhT hi/lo.
// ---------------------------------------------------------------------------
__global__ __launch_bounds__(256) void k_g1mma(const float* __restrict__ bW) {
    extern __shared__ __align__(128) char dsm[];
    __shared__ float bWs[128];
    const int tid = threadIdx.x, wid = tid >> 5, lane = tid & 31;
    const int m0 = blockIdx.x * 64, n0 = blockIdx.y * 128;
    const int wm = wid >> 2, wn = wid & 3;

    if (tid < 128) bWs[tid] = bW[n0 + tid];

    const __half* Ah = g_xh + (size_t)m0 * VD;
    const __half* Al = g_xl + (size_t)m0 * VD;
    const __half* Bh = g_W16h + (size_t)n0 * VD;
    const __half* Bl = g_W16l + (size_t)n0 * VD;

    const uint32_t s0 = smem_u32(dsm);

    auto load_chunk = [&](int c) {
        const uint32_t st = s0 + (c & 1) * STAGE_G;
        const int jt = c * KCH;
        {
            int row = tid >> 2, cc = tid & 3;
            uint32_t o = (uint32_t)(row * 80 + cc * 16);
            const size_t go = (size_t)row * VD + jt + cc * 8;
            cp16(st + o,        Ah + go);
            cp16(st + 5120 + o, Al + go);
        }
        for (int t = tid; t < 512; t += 256) {
            int row = t >> 2, cc = t & 3;
            uint32_t o = (uint32_t)(row * 80 + cc * 16);
            const size_t go = (size_t)row * VD + jt + cc * 8;
            cp16(st + 10240 + o, Bh + go);
            cp16(st + 20480 + o, Bl + go);
        }
        CP_COMMIT();
    };

    float acc[2][4][4];
#pragma unroll
    for (int mt = 0; mt < 2; mt++)
#pragma unroll
        for (int nt = 0; nt < 4; nt++)
#pragma unroll
            for (int q = 0; q < 4; q++) acc[mt][nt][q] = 0.f;

    const int aRow = wm * 32 + (lane & 7) + ((lane >> 3) & 1) * 8;
    const int aC16 = ((lane >> 4) & 1) * 16;
    const int bRow = wn * 32 + (lane & 7) + ((lane >> 4) & 1) * 8;
    const int bC16 = ((lane >> 3) & 1) * 16;

    load_chunk(0);

    for (int c = 0; c < NCHG; c++) {
        if (c + 1 < NCHG) { load_chunk(c + 1); CP_WAIT1(); }
        else             { CP_WAIT0(); }
        __syncthreads();
        const uint32_t st = s0 + (c & 1) * STAGE_G;
#pragma unroll
        for (int ks = 0; ks < 2; ks++) {
            const int koff = ks * 32;
            uint32_t ah[2][4], al[2][4], bh[2][4], bl[2][4];
#pragma unroll
            for (int mt = 0; mt < 2; mt++) {
                uint32_t ao = st + (uint32_t)((aRow + mt * 16) * 80 + aC16 + koff);
                ldmx4(ah[mt], ao);
                ldmx4(al[mt], ao + 5120);
            }
#pragma unroll
            for (int p = 0; p < 2; p++) {
                uint32_t bo = st + 10240 +
                              (uint32_t)((bRow + p * 16) * 80 + bC16 + koff);
                ldmx4(bh[p], bo);
                ldmx4(bl[p], bo + 10240);
            }
#pragma unroll
            for (int mt = 0; mt < 2; mt++) {
#pragma unroll
                for (int nt = 0; nt < 4; nt++) {
                    const int p = nt >> 1, hf = (nt & 1) * 2;
                    mma16816(acc[mt][nt], ah[mt], bh[p][hf], bh[p][hf + 1]);
                    mma16816(acc[mt][nt], ah[mt], bl[p][hf], bl[p][hf + 1]);
                    mma16816(acc[mt][nt], al[mt], bh[p][hf], bh[p][hf + 1]);
                }
            }
        }
        __syncthreads();
    }

    float* s = (float*)dsm;   // [64][129]
#pragma unroll
    for (int mt = 0; mt < 2; mt++) {
        const int ml = wm * 32 + mt * 16 + (lane >> 2);
#pragma unroll
        for (int nt = 0; nt < 4; nt++) {
            const int nl = wn * 32 + nt * 8 + (lane & 3) * 2;
            s[ml * 129 + nl]           = acc[mt][nt][0];
            s[ml * 129 + nl + 1]       = acc[mt][nt][1];
            s[(ml + 8) * 129 + nl]     = acc[mt][nt][2];
            s[(ml + 8) * 129 + nl + 1] = acc[mt][nt][3];
        }
    }
    __syncthreads();

    const int b  = m0 / NODES;
    const int j0 = m0 % NODES;
#pragma unroll
    for (int it = 0; it < 16; it++) {
        const int f = wid * 16 + it;
        const float bw = bWs[f];
        float v0 = s[(2 * lane) * 129 + f] + bw;
        float v1 = s[(2 * lane + 1) * 129 + f] + bw;
        __half2 h, l;
        split2(v0, v1, h, l);
        size_t o = ((size_t)(b * FD + n0 + f)) * NODES + j0 + 2 * lane;
        *(__half2*)&g_WhT_hi[o] = h;
        *(__half2*)&g_WhT_lo[o] = l;
    }
}

// ---------------------------------------------------------------------------
// k_mma2f: FUSED masked-softmax + P @ Wh^T + deferred norm + ELU.
// 2 syncs/chunk: prefetch head start (loadB before wait) AND exp-under-MMA.
// ---------------------------------------------------------------------------
__global__ __launch_bounds__(256) void k_mma2f(float* __restrict__ out) {
    extern __shared__ __align__(128) char dsm[];
    float*    Wh2s = (float*)dsm;                 // 1600
    float*    wh1s = Wh2s + NODES;                // 64
    float*    ms   = wh1s + 64;                   // 64
    uint32_t* bms  = (uint32_t*)(ms + 64);        // 64*50

    const int tid = threadIdx.x, wid = tid >> 5, lane = tid & 31;
    const int m0 = blockIdx.x * 64, n0 = blockIdx.y * 128, b = blockIdx.z;
    const int wm = wid >> 2, wn = wid & 3;

    const __half* Bh = g_WhT_hi + ((size_t)b * FD + n0) * NODES;
    const __half* Bl = g_WhT_lo + ((size_t)b * FD + n0) * NODES;

    const uint32_t s0 = smem_u32(dsm);
    const uint32_t sA = s0 + ABASE;
    const uint32_t sB = s0 + BBASE;

    auto loadB = [&](int c) {
        const uint32_t st = sB + (c & 1) * 20480;
        const int jt = c * KCH;
        for (int t = tid; t < 512; t += 256) {
            int row = t >> 2, cc = t & 3;
            uint32_t o = (uint32_t)(row * 80 + cc * 16);
            const size_t go = (size_t)row * NODES + jt + cc * 8;
            cp16(st + o,         Bh + go);
            cp16(st + 10240 + o, Bl + go);
        }
        CP_COMMIT();
    };

    loadB(0);

    // ---- fill smem: Wh2 row, Wh1 tile, bitmask rows ----
    for (int j = tid; j < NODES; j += 256)
        Wh2s[j] = g_Wh2[b * NODES + j];
    if (tid < 64)
        wh1s[tid] = g_Wh1[b * NODES + m0 + tid];
    for (int t = tid; t < 64 * 50; t += 256)
        bms[t] = g_bm[m0 * 50 + t];
    __syncthreads();

    // ---- prologue: masked max per row (warp wid -> rows wid*8..wid*8+7) ----
#pragma unroll
    for (int rr = 0; rr < 8; rr++) {
        const int r = wid * 8 + rr;
        const uint32_t* bmr = &bms[r * 50];
        float mx = -3e38f;
        for (int w = 0; w < 50; w++)
            if ((bmr[w] >> lane) & 1) mx = fmaxf(mx, Wh2s[w * 32 + lane]);
#pragma unroll
        for (int o = 16; o; o >>= 1) mx = fmaxf(mx, __shfl_xor_sync(0xFFFFFFFFu, mx, o));
        if (lane == 0) {
            float em = wh1s[r] + mx;
            em = em > 0.f ? em : 0.2f * em;
            ms[r] = (mx > -1e30f) ? em : -1e9f;
        }
    }
    __syncthreads();

    float acc[2][4][4];
    float accs[2][4];
#pragma unroll
    for (int mt = 0; mt < 2; mt++) {
#pragma unroll
        for (int nt = 0; nt < 4; nt++)
#pragma unroll
            for (int q = 0; q < 4; q++) acc[mt][nt][q] = 0.f;
#pragma unroll
        for (int q = 0; q < 4; q++) accs[mt][q] = 0.f;
    }

    const int aRow = wm * 32 + (lane & 7) + ((lane >> 3) & 1) * 8;
    const int aC16 = ((lane >> 4) & 1) * 16;
    const int bRow = wn * 32 + (lane & 7) + ((lane >> 4) & 1) * 8;
    const int bC16 = ((lane >> 3) & 1) * 16;
    const uint32_t ONES2 = 0x3C003C00u;  // half2(1.0, 1.0)

    // P-tile compute mapping: thread -> row pr (0..63), col group pq (0..3)
    const int pr = tid >> 2, pq = tid & 3;
    const float wh1r = wh1s[pr];
    const float mr   = ms[pr];
    const uint32_t* bmp = &bms[pr * 50];

    // P(c) tile -> A buffer (c&1). (-1e9 select keeps empty rows uniform.)
    auto computeA = [&](int c) {
        const int jt = c * KCH;
        const uint32_t word = bmp[c];          // KCH == 32: one word per chunk
        uint32_t uv[4];
#pragma unroll
        for (int u = 0; u < 4; u++) {
            const int jj = pq * 8 + u * 2;
            float2 w2 = *(const float2*)&Wh2s[jt + jj];
            float e0 = wh1r + w2.x; e0 = e0 > 0.f ? e0 : 0.2f * e0;
            float e1 = wh1r + w2.y; e1 = e1 > 0.f ? e1 : 0.2f * e1;
            float x0 = __expf((((word >> jj) & 1)       ? e0 : -1e9f) - mr);
            float x1 = __expf((((word >> (jj + 1)) & 1) ? e1 : -1e9f) - mr);
            __half2 hh = __halves2half2(__float2half_rn(x0), __float2half_rn(x1));
            uv[u] = *(uint32_t*)&hh;
        }
        *(uint4*)(dsm + ABASE + (c & 1) * 5120 + pr * 80 + pq * 16) =
            make_uint4(uv[0], uv[1], uv[2], uv[3]);
    };

    computeA(0);   // A(0); visible after X(0)

    for (int c = 0; c < NCH; c++) {
        // prefetch head start: issue B(c+1) BEFORE waiting for B(c)
        if (c + 1 < NCH) { loadB(c + 1); CP_WAIT1(); }
        else             { CP_WAIT0(); }
        __syncthreads();     // X(c): A(c)+B(c) published

        const uint32_t stA = sA + (c & 1) * 5120;
        const uint32_t stB = sB + (c & 1) * 20480;
#pragma unroll
        for (int ks = 0; ks < 2; ks++) {
            const int koff = ks * 32;
            uint32_t ah[2][4], bh[2][4], bl[2][4];
#pragma unroll
            for (int mt = 0; mt < 2; mt++) {
                uint32_t ao = stA + (uint32_t)((aRow + mt * 16) * 80 + aC16 + koff);
                ldmx4(ah[mt], ao);
            }
#pragma unroll
            for (int p = 0; p < 2; p++) {
                uint32_t bo = stB + (uint32_t)((bRow + p * 16) * 80 + bC16 + koff);
                ldmx4(bh[p], bo);
                ldmx4(bl[p], bo + 10240);
            }
#pragma unroll
            for (int mt = 0; mt < 2; mt++) {
#pragma unroll
                for (int nt = 0; nt < 4; nt++) {
                    const int p = nt >> 1, hf = (nt & 1) * 2;
                    mma16816(acc[mt][nt], ah[mt], bh[p][hf], bh[p][hf + 1]);
                    mma16816(acc[mt][nt], ah[mt], bl[p][hf], bl[p][hf + 1]);
                }
                mma16816(accs[mt], ah[mt], ONES2, ONES2);  // row sums
            }
        }

        // exp work for chunk c+1 overlaps chunk-c HMMA drain
        if (c + 1 < NCH) computeA(c + 1);

        __syncthreads();     // Y(c): protects next loadB/computeA buffer reuse
    }

    // ---- epilogue: scale by 1/rowsum, ELU, store ----
#pragma unroll
    for (int mt = 0; mt < 2; mt++) {
        const int mA = m0 + wm * 32 + mt * 16 + (lane >> 2);
        const float ilA = 1.f / accs[mt][0];
        const float ilB = 1.f / accs[mt][2];
#pragma unroll
        for (int nt = 0; nt < 4; nt++) {
            const int n = n0 + wn * 32 + nt * 8 + (lane & 3) * 2;
            float* op = out + ((size_t)(b * NODES) + mA) * FD + n;
            float d0 = acc[mt][nt][0] * ilA, d1 = acc[mt][nt][1] * ilA;
            float d2 = acc[mt][nt][2] * ilB, d3 = acc[mt][nt][3] * ilB;
            float2 v0, v1;
            v0.x = d0 > 0.f ? d0 : (__expf(d0) - 1.f);
            v0.y = d1 > 0.f ? d1 : (__expf(d1) - 1.f);
            v1.x = d2 > 0.f ? d2 : (__expf(d2) - 1.f);
            v1.y = d3 > 0.f ? d3 : (__expf(d3) - 1.f);
            *(float2*)op = v0;
            *(float2*)(op + 8 * FD) = v1;
        }
    }
}

// ---------------------------------------------------------------------------
extern "C" void kernel_launch(void* const* d_in, const int* in_sizes, int n_in,
                              void* d_out, int out_size) {
    const float* h   = (const float*)d_in[0];
    const int*   adj = (const int*)  d_in[1];
    const float* W   = (const float*)d_in[2];
    const float* bW  = (const float*)d_in[3];
    const float* ai  = (const float*)d_in[4];
    const float* bi  = (const float*)d_in[5];
    const float* aj  = (const float*)d_in[6];
    const float* bj  = (const float*)d_in[7];
    float* out = (float*)d_out;

    cudaFuncSetAttribute(k_g1mma, cudaFuncAttributeMaxDynamicSharedMemorySize, SMEM_G);
    cudaFuncSetAttribute(k_mma2f, cudaFuncAttributeMaxDynamicSharedMemorySize, SMEM_M);

    k_split_x<<<(MTOT * VD / 4) / 256, 256>>>((const float4*)h);
    k_wprep<<<1, 256>>>(W, bW, ai, bi, aj, bj);
    k_projx<<<MTOT / 8, 256>>>(h);
    k_bm<<<NODES / 8, 256>>>(adj);
    k_g1mma<<<dim3(MTOT / 64, 2), 256, SMEM_G>>>(bW);
    dim3 gm(NODES / 64, FD / 128, BB);
    k_mma2f<<<gm, 256, SMEM_M>>>(out);
}

// round 11
// speedup vs baseline: 1.4490x; 1.2960x over previous
#include <cuda_runtime.h>
#include <cuda_fp16.h>
#include <cstdint>

#define BB      8
#define NODES   1600
#define VD      256
#define FD      256
#define MTOT    (BB * NODES)   // 12800
#define KCH     32
#define NCH     (NODES / KCH)  // 50  (k_mma2f)
#define NCHG    (VD / KCH)     // 8   (k_g1mma)
// k_g1mma stages (A hi/lo + B hi/lo)
#define STAGE_G 30720
#define SMEM_G  (2 * STAGE_G)
// k_mma2f smem layout (bytes from base):
//   Wh2s 6400 | wh1s 256 | ms 256 | rows 256 | bm 12800 | A0 5120 | A1 5120 | B0 10240 | B1 10240
#define ABASE   19968
#define BBASE   (ABASE + 2 * 5120)      // 30208
#define SMEM_M  (BBASE + 2 * 10240)     // 50688

// ---------------- scratch (device globals; allocation-free) ----------------
__device__ float                 g_Wh1 [MTOT];
__device__ float                 g_Wh2 [MTOT];
__device__ float                 g_ui[VD], g_uj[VD];
__device__ float                 g_ci, g_cj;
__device__ uint32_t              g_bm[NODES * 50];
__device__ __align__(128) __half g_xh[(size_t)MTOT * VD];
__device__ __align__(128) __half g_xl[(size_t)MTOT * VD];
__device__ __align__(128) __half g_W16h[FD * VD];
__device__ __align__(128) __half g_W16l[FD * VD];
__device__ __align__(128) __half g_WhT_hi[BB * FD * NODES];

// ---------------- PTX helpers (sm_80-era only) ----------------
__device__ __forceinline__ uint32_t smem_u32(const void* p) {
    uint32_t a;
    asm("{ .reg .u64 t; cvta.to.shared.u64 t, %1; cvt.u32.u64 %0, t; }" : "=r"(a) : "l"(p));
    return a;
}
__device__ __forceinline__ void cp16(uint32_t dst, const void* src) {
    asm volatile("cp.async.cg.shared.global [%0], [%1], 16;" :: "r"(dst), "l"(src) : "memory");
}
#define CP_COMMIT() asm volatile("cp.async.commit_group;" ::: "memory")
#define CP_WAIT1()  asm volatile("cp.async.wait_group 1;" ::: "memory")
#define CP_WAIT0()  asm volatile("cp.async.wait_group 0;" ::: "memory")

__device__ __forceinline__ void ldmx4(uint32_t* r, uint32_t addr) {
    asm volatile("ldmatrix.sync.aligned.m8n8.x4.shared.b16 {%0,%1,%2,%3}, [%4];"
                 : "=r"(r[0]), "=r"(r[1]), "=r"(r[2]), "=r"(r[3]) : "r"(addr));
}
__device__ __forceinline__ void mma16816(float* c, const uint32_t* a,
                                         uint32_t b0, uint32_t b1) {
    asm volatile(
        "mma.sync.aligned.m16n8k16.row.col.f32.f16.f16.f32 "
        "{%0,%1,%2,%3}, {%4,%5,%6,%7}, {%8,%9}, {%0,%1,%2,%3};"
        : "+f"(c[0]), "+f"(c[1]), "+f"(c[2]), "+f"(c[3])
        : "r"(a[0]), "r"(a[1]), "r"(a[2]), "r"(a[3]), "r"(b0), "r"(b1));
}
__device__ __forceinline__ void split2(float v0, float v1, __half2& h, __half2& l) {
    __half h0 = __float2half_rn(v0), h1 = __float2half_rn(v1);
    h = __halves2half2(h0, h1);
    l = __halves2half2(__float2half_rn(v0 - __half2float(h0)),
                       __float2half_rn(v1 - __half2float(h1)));
}

// ---------------------------------------------------------------------------
// k_split_x: x fp32 -> xh/xl fp16 split
// ---------------------------------------------------------------------------
__global__ __launch_bounds__(256) void k_split_x(const float4* __restrict__ x) {
    const size_t idx = (size_t)blockIdx.x * 256 + threadIdx.x;
    float4 v = x[idx];
    __half2 h01, l01, h23, l23;
    split2(v.x, v.y, h01, l01);
    split2(v.z, v.w, h23, l23);
    __half2* ph = (__half2*)&g_xh[idx * 4];
    __half2* pl = (__half2*)&g_xl[idx * 4];
    ph[0] = h01; ph[1] = h23;
    pl[0] = l01; pl[1] = l23;
}

// ---------------------------------------------------------------------------
// k_wprep: u_i = W^T ai, u_j = W^T aj, c_i/c_j; W -> fp16 split. One CTA.
// ---------------------------------------------------------------------------
__global__ __launch_bounds__(256) void k_wprep(const float* __restrict__ W,
                                               const float* __restrict__ bW,
                                               const float* __restrict__ ai,
                                               const float* __restrict__ bi,
                                               const float* __restrict__ aj,
                                               const float* __restrict__ bj) {
    __shared__ float red[16];
    const int v = threadIdx.x;
    float ui = 0.f, uj = 0.f;
    for (int f = 0; f < FD; f++) {
        float w = W[f * VD + v];
        ui += ai[f] * w;
        uj += aj[f] * w;
    }
    g_ui[v] = ui;
    g_uj[v] = uj;

    for (int t = v; t < FD * VD / 2; t += 256) {
        float2 w2 = ((const float2*)W)[t];
        __half2 h, l;
        split2(w2.x, w2.y, h, l);
        *(__half2*)&g_W16h[2 * t] = h;
        *(__half2*)&g_W16l[2 * t] = l;
    }

    float p1 = ai[v] * bW[v];
    float p2 = aj[v] * bW[v];
    const int warp = v >> 5, lane = v & 31;
#pragma unroll
    for (int o = 16; o; o >>= 1) {
        p1 += __shfl_xor_sync(0xFFFFFFFFu, p1, o);
        p2 += __shfl_xor_sync(0xFFFFFFFFu, p2, o);
    }
    if (lane == 0) { red[warp] = p1; red[8 + warp] = p2; }
    __syncthreads();
    if (v == 0) {
        float c1 = bi[0], c2 = bj[0];
        for (int w = 0; w < 8; w++) { c1 += red[w]; c2 += red[8 + w]; }
        g_ci = c1; g_cj = c2;
    }
}

// ---------------------------------------------------------------------------
// k_projx: Wh1/Wh2 directly from x (warp per row)
// ---------------------------------------------------------------------------
__global__ __launch_bounds__(256) void k_projx(const float* __restrict__ x) {
    const int gwarp = (blockIdx.x * blockDim.x + threadIdx.x) >> 5;
    const int lane = threadIdx.x & 31;
    const float* row = x + (size_t)gwarp * VD;
    float s1 = 0.f, s2 = 0.f;
#pragma unroll
    for (int q = 0; q < 8; q++) {
        const int k = lane + 32 * q;
        float v = row[k];
        s1 += v * g_ui[k];
        s2 += v * g_uj[k];
    }
#pragma unroll
    for (int o = 16; o; o >>= 1) {
        s1 += __shfl_xor_sync(0xFFFFFFFFu, s1, o);
        s2 += __shfl_xor_sync(0xFFFFFFFFu, s2, o);
    }
    if (lane == 0) {
        g_Wh1[gwarp] = s1 + g_ci;
        g_Wh2[gwarp] = s2 + g_cj;
    }
}

// ---------------------------------------------------------------------------
// k_bm: adjacency -> bitmask (once; batch-independent). Warp per row.
// ---------------------------------------------------------------------------
__global__ __launch_bounds__(256) void k_bm(const int* __restrict__ adj) {
    const int row = blockIdx.x * 8 + (threadIdx.x >> 5);
    const int lane = threadIdx.x & 31;
    const int* ar = adj + (size_t)row * NODES;
    for (int w = 0; w < 50; w++) {
        uint32_t bit = __ballot_sync(0xFFFFFFFFu, ar[w * 32 + lane] > 0);
        if (lane == 0) g_bm[row * 50 + w] = bit;
    }
}

// ---------------------------------------------------------------------------
// k_g1mma: Wh = x @ W^T (+bW), 3-term fp16 hi/lo; epilogue -> WhT hi ONLY.
// ---------------------------------------------------------------------------
__global__ __launch_bounds__(256) void k_g1mma(const float* __restrict__ bW) {
    extern __shared__ __align__(128) char dsm[];
    __shared__ float bWs[128];
    const int tid = threadIdx.x, wid = tid >> 5, lane = tid & 31;
    const int m0 = blockIdx.x * 64, n0 = blockIdx.y * 128;
    const int wm = wid >> 2, wn = wid & 3;

    if (tid < 128) bWs[tid] = bW[n0 + tid];

    const __half* Ah = g_xh + (size_t)m0 * VD;
    const __half* Al = g_xl + (size_t)m0 * VD;
    const __half* Bh = g_W16h + (size_t)n0 * VD;
    const __half* Bl = g_W16l + (size_t)n0 * VD;

    const uint32_t s0 = smem_u32(dsm);

    auto load_chunk = [&](int c) {
        const uint32_t st = s0 + (c & 1) * STAGE_G;
        const int jt = c * KCH;
        {
            int row = tid >> 2, cc = tid & 3;
            uint32_t o = (uint32_t)(row * 80 + cc * 16);
            const size_t go = (size_t)row * VD + jt + cc * 8;
            cp16(st + o,        Ah + go);
            cp16(st + 5120 + o, Al + go);
        }
        for (int t = tid; t < 512; t += 256) {
            int row = t >> 2, cc = t & 3;
            uint32_t o = (uint32_t)(row * 80 + cc * 16);
            const size_t go = (size_t)row * VD + jt + cc * 8;
            cp16(st + 10240 + o, Bh + go);
            cp16(st + 20480 + o, Bl + go);
        }
        CP_COMMIT();
    };

    float acc[2][4][4];
#pragma unroll
    for (int mt = 0; mt < 2; mt++)
#pragma unroll
        for (int nt = 0; nt < 4; nt++)
#pragma unroll
            for (int q = 0; q < 4; q++) acc[mt][nt][q] = 0.f;

    const int aRow = wm * 32 + (lane & 7) + ((lane >> 3) & 1) * 8;
    const int aC16 = ((lane >> 4) & 1) * 16;
    const int bRow = wn * 32 + (lane & 7) + ((lane >> 4) & 1) * 8;
    const int bC16 = ((lane >> 3) & 1) * 16;

    load_chunk(0);

    for (int c = 0; c < NCHG; c++) {
        if (c + 1 < NCHG) { load_chunk(c + 1); CP_WAIT1(); }
        else             { CP_WAIT0(); }
        __syncthreads();
        const uint32_t st = s0 + (c & 1) * STAGE_G;
#pragma unroll
        for (int ks = 0; ks < 2; ks++) {
            const int koff = ks * 32;
            uint32_t ah[2][4], al[2][4], bh[2][4], bl[2][4];
#pragma unroll
            for (int mt = 0; mt < 2; mt++) {
                uint32_t ao = st + (uint32_t)((aRow + mt * 16) * 80 + aC16 + koff);
                ldmx4(ah[mt], ao);
                ldmx4(al[mt], ao + 5120);
            }
#pragma unroll
            for (int p = 0; p < 2; p++) {
                uint32_t bo = st + 10240 +
                              (uint32_t)((bRow + p * 16) * 80 + bC16 + koff);
                ldmx4(bh[p], bo);
                ldmx4(bl[p], bo + 10240);
            }
#pragma unroll
            for (int mt = 0; mt < 2; mt++) {
#pragma unroll
                for (int nt = 0; nt < 4; nt++) {
                    const int p = nt >> 1, hf = (nt & 1) * 2;
                    mma16816(acc[mt][nt], ah[mt], bh[p][hf], bh[p][hf + 1]);
                    mma16816(acc[mt][nt], ah[mt], bl[p][hf], bl[p][hf + 1]);
                    mma16816(acc[mt][nt], al[mt], bh[p][hf], bh[p][hf + 1]);
                }
            }
        }
        __syncthreads();
    }

    float* s = (float*)dsm;   // [64][129]
#pragma unroll
    for (int mt = 0; mt < 2; mt++) {
        const int ml = wm * 32 + mt * 16 + (lane >> 2);
#pragma unroll
        for (int nt = 0; nt < 4; nt++) {
            const int nl = wn * 32 + nt * 8 + (lane & 3) * 2;
            s[ml * 129 + nl]           = acc[mt][nt][0];
            s[ml * 129 + nl + 1]       = acc[mt][nt][1];
            s[(ml + 8) * 129 + nl]     = acc[mt][nt][2];
            s[(ml + 8) * 129 + nl + 1] = acc[mt][nt][3];
        }
    }
    __syncthreads();

    const int b  = m0 / NODES;
    const int j0 = m0 % NODES;
#pragma unroll
    for (int it = 0; it < 16; it++) {
        const int f = wid * 16 + it;
        const float bw = bWs[f];
        float v0 = s[(2 * lane) * 129 + f] + bw;
        float v1 = s[(2 * lane + 1) * 129 + f] + bw;
        __half2 h = __halves2half2(__float2half_rn(v0), __float2half_rn(v1));
        size_t o = ((size_t)(b * FD + n0 + f)) * NODES + j0 + 2 * lane;
        *(__half2*)&g_WhT_hi[o] = h;
    }
}

// ---------------------------------------------------------------------------
// k_mma2f: FUSED masked-softmax + P @ Wh^T + deferred norm + ELU.
// Single-precision B (Wh hi only); row sums accumulated in ALU during
// computeA (overlapped), reduced across pq lanes at loop end.
// ---------------------------------------------------------------------------
__global__ __launch_bounds__(256) void k_mma2f(float* __restrict__ out) {
    extern __shared__ __align__(128) char dsm[];
    float*    Wh2s = (float*)dsm;                 // 1600 @ 0
    float*    wh1s = Wh2s + NODES;                // 64   @ 6400
    float*    ms   = wh1s + 64;                   // 64   @ 6656
    float*    rows = ms + 64;                     // 64   @ 6912
    uint32_t* bms  = (uint32_t*)(rows + 64);      // 64*50 @ 7168

    const int tid = threadIdx.x, wid = tid >> 5, lane = tid & 31;
    const int m0 = blockIdx.x * 64, n0 = blockIdx.y * 128, b = blockIdx.z;
    const int wm = wid >> 2, wn = wid & 3;

    const __half* Bh = g_WhT_hi + ((size_t)b * FD + n0) * NODES;

    const uint32_t s0 = smem_u32(dsm);
    const uint32_t sA = s0 + ABASE;
    const uint32_t sB = s0 + BBASE;

    auto loadB = [&](int c) {
        const uint32_t st = sB + (c & 1) * 10240;
        const int jt = c * KCH;
        for (int t = tid; t < 512; t += 256) {
            int row = t >> 2, cc = t & 3;
            uint32_t o = (uint32_t)(row * 80 + cc * 16);
            cp16(st + o, Bh + (size_t)row * NODES + jt + cc * 8);
        }
        CP_COMMIT();
    };

    loadB(0);

    // ---- fill smem: Wh2 row, Wh1 tile, bitmask rows ----
    for (int j = tid; j < NODES; j += 256)
        Wh2s[j] = g_Wh2[b * NODES + j];
    if (tid < 64)
        wh1s[tid] = g_Wh1[b * NODES + m0 + tid];
    for (int t = tid; t < 64 * 50; t += 256)
        bms[t] = g_bm[m0 * 50 + t];
    __syncthreads();

    // ---- prologue: masked max per row (warp wid -> rows wid*8..wid*8+7) ----
#pragma unroll
    for (int rr = 0; rr < 8; rr++) {
        const int r = wid * 8 + rr;
        const uint32_t* bmr = &bms[r * 50];
        float mx = -3e38f;
        for (int w = 0; w < 50; w++)
            if ((bmr[w] >> lane) & 1) mx = fmaxf(mx, Wh2s[w * 32 + lane]);
#pragma unroll
        for (int o = 16; o; o >>= 1) mx = fmaxf(mx, __shfl_xor_sync(0xFFFFFFFFu, mx, o));
        if (lane == 0) {
            float em = wh1s[r] + mx;
            em = em > 0.f ? em : 0.2f * em;
            ms[r] = (mx > -1e30f) ? em : -1e9f;
        }
    }
    __syncthreads();

    float acc[2][4][4];
#pragma unroll
    for (int mt = 0; mt < 2; mt++)
#pragma unroll
        for (int nt = 0; nt < 4; nt++)
#pragma unroll
            for (int q = 0; q < 4; q++) acc[mt][nt][q] = 0.f;

    const int aRow = wm * 32 + (lane & 7) + ((lane >> 3) & 1) * 8;
    const int aC16 = ((lane >> 4) & 1) * 16;
    const int bRow = wn * 32 + (lane & 7) + ((lane >> 4) & 1) * 8;
    const int bC16 = ((lane >> 3) & 1) * 16;

    // P-tile compute mapping: thread -> row pr (0..63), col group pq (0..3)
    const int pr = tid >> 2, pq = tid & 3;
    const float wh1r = wh1s[pr];
    const float mr   = ms[pr];
    const uint32_t* bmp = &bms[pr * 50];
    float sacc = 0.f;   // partial row sum of ROUNDED P (this thread's 8 cols/chunk)

    // P(c) tile -> A buffer (c&1); accumulate rounded-P row sum.
    auto computeA = [&](int c) {
        const int jt = c * KCH;
        const uint32_t word = bmp[c];          // KCH == 32: one word per chunk
        uint32_t uv[4];
#pragma unroll
        for (int u = 0; u < 4; u++) {
            const int jj = pq * 8 + u * 2;
            float2 w2 = *(const float2*)&Wh2s[jt + jj];
            float e0 = wh1r + w2.x; e0 = e0 > 0.f ? e0 : 0.2f * e0;
            float e1 = wh1r + w2.y; e1 = e1 > 0.f ? e1 : 0.2f * e1;
            float x0 = __expf((((word >> jj) & 1)       ? e0 : -1e9f) - mr);
            float x1 = __expf((((word >> (jj + 1)) & 1) ? e1 : -1e9f) - mr);
            __half2 hh = __halves2half2(__float2half_rn(x0), __float2half_rn(x1));
            uv[u] = *(uint32_t*)&hh;
            sacc += __low2float(hh) + __high2float(hh);
        }
        *(uint4*)(dsm + ABASE + (c & 1) * 5120 + pr * 80 + pq * 16) =
            make_uint4(uv[0], uv[1], uv[2], uv[3]);
    };

    computeA(0);   // A(0); visible after X(0)

    for (int c = 0; c < NCH; c++) {
        // prefetch head start: issue B(c+1) BEFORE waiting for B(c)
        if (c + 1 < NCH) { loadB(c + 1); CP_WAIT1(); }
        else             { CP_WAIT0(); }
        __syncthreads();     // X(c): A(c)+B(c) published

        const uint32_t stA = sA + (c & 1) * 5120;
        const uint32_t stB = sB + (c & 1) * 10240;
#pragma unroll
        for (int ks = 0; ks < 2; ks++) {
            const int koff = ks * 32;
            uint32_t ah[2][4], bh[2][4];
#pragma unroll
            for (int mt = 0; mt < 2; mt++) {
                uint32_t ao = stA + (uint32_t)((aRow + mt * 16) * 80 + aC16 + koff);
                ldmx4(ah[mt], ao);
            }
#pragma unroll
            for (int p = 0; p < 2; p++) {
                uint32_t bo = stB + (uint32_t)((bRow + p * 16) * 80 + bC16 + koff);
                ldmx4(bh[p], bo);
            }
#pragma unroll
            for (int mt = 0; mt < 2; mt++) {
#pragma unroll
                for (int nt = 0; nt < 4; nt++) {
                    const int p = nt >> 1, hf = (nt & 1) * 2;
                    mma16816(acc[mt][nt], ah[mt], bh[p][hf], bh[p][hf + 1]);
                }
            }
        }

        // exp work for chunk c+1 overlaps chunk-c HMMA drain
        if (c + 1 < NCH) computeA(c + 1);

        __syncthreads();     // Y(c): protects next loadB/computeA buffer reuse
    }

    // ---- publish row sums (reduce across the 4 pq lanes of each row) ----
    sacc += __shfl_xor_sync(0xFFFFFFFFu, sacc, 1);
    sacc += __shfl_xor_sync(0xFFFFFFFFu, sacc, 2);
    if (pq == 0) rows[pr] = sacc;
    __syncthreads();

    // ---- epilogue: scale by 1/rowsum, ELU, store ----
#pragma unroll
    for (int mt = 0; mt < 2; mt++) {
        const int ml = wm * 32 + mt * 16 + (lane >> 2);
        const int mA = m0 + ml;
        const float ilA = 1.f / rows[ml];
        const float ilB = 1.f / rows[ml + 8];
#pragma unroll
        for (int nt = 0; nt < 4; nt++) {
            const int n = n0 + wn * 32 + nt * 8 + (lane & 3) * 2;
            float* op = out + ((size_t)(b * NODES) + mA) * FD + n;
            float d0 = acc[mt][nt][0] * ilA, d1 = acc[mt][nt][1] * ilA;
            float d2 = acc[mt][nt][2] * ilB, d3 = acc[mt][nt][3] * ilB;
            float2 v0, v1;
            v0.x = d0 > 0.f ? d0 : (__expf(d0) - 1.f);
            v0.y = d1 > 0.f ? d1 : (__expf(d1) - 1.f);
            v1.x = d2 > 0.f ? d2 : (__expf(d2) - 1.f);
            v1.y = d3 > 0.f ? d3 : (__expf(d3) - 1.f);
            *(float2*)op = v0;
            *(float2*)(op + 8 * FD) = v1;
        }
    }
}

// ---------------------------------------------------------------------------
extern "C" void kernel_launch(void* const* d_in, const int* in_sizes, int n_in,
                              void* d_out, int out_size) {
    const float* h   = (const float*)d_in[0];
    const int*   adj = (const int*)  d_in[1];
    const float* W   = (const float*)d_in[2];
    const float* bW  = (const float*)d_in[3];
    const float* ai  = (const float*)d_in[4];
    const float* bi  = (const float*)d_in[5];
    const float* aj  = (const float*)d_in[6];
    const float* bj  = (const float*)d_in[7];
    float* out = (float*)d_out;

    cudaFuncSetAttribute(k_g1mma, cudaFuncAttributeMaxDynamicSharedMemorySize, SMEM_G);
    cudaFuncSetAttribute(k_mma2f, cudaFuncAttributeMaxDynamicSharedMemorySize, SMEM_M);

    k_split_x<<<(MTOT * VD / 4) / 256, 256>>>((const float4*)h);
    k_wprep<<<1, 256>>>(W, bW, ai, bi, aj, bj);
    k_projx<<<MTOT / 8, 256>>>(h);
    k_bm<<<NODES / 8, 256>>>(adj);
    k_g1mma<<<dim3(MTOT / 64, 2), 256, SMEM_G>>>(bW);
    dim3 gm(NODES / 64, FD / 128, BB);
    k_mma2f<<<gm, 256, SMEM_M>>>(out);
}

// round 12
// speedup vs baseline: 1.4832x; 1.0236x over previous
#include <cuda_runtime.h>
#include <cuda_fp16.h>
#include <cstdint>

#define BB      8
#define NODES   1600
#define VD      256
#define FD      256
#define MTOT    (BB * NODES)   // 12800
#define KCH     32
#define NCH     (NODES / KCH)  // 50  (k_mma2f)
#define NCHG    (VD / KCH)     // 8   (k_g1mma)
// k_g1mma stages (A hi + B hi/lo)
#define STAGE_G 25600
#define SMEM_G  (2 * STAGE_G)
// k_mma2f smem: header 19968 | A x3 @ ABASE | B x3 @ BBASE
#define ABASE   19968
#define BBASE   (ABASE + 3 * 5120)      // 35328
#define SMEM_M  (BBASE + 3 * 10240)     // 66048

// ---------------- scratch (device globals; allocation-free) ----------------
__device__ float                 g_Wh1 [MTOT];
__device__ float                 g_Wh2 [MTOT];
__device__ float                 g_ui[VD], g_uj[VD];
__device__ float                 g_ci, g_cj;
__device__ uint32_t              g_bm[NODES * 50];
__device__ __align__(128) __half g_xh[(size_t)MTOT * VD];
__device__ __align__(128) __half g_W16h[FD * VD];
__device__ __align__(128) __half g_W16l[FD * VD];
__device__ __align__(128) __half g_WhT_hi[BB * FD * NODES];

// ---------------- PTX helpers (sm_80-era only) ----------------
__device__ __forceinline__ uint32_t smem_u32(const void* p) {
    uint32_t a;
    asm("{ .reg .u64 t; cvta.to.shared.u64 t, %1; cvt.u32.u64 %0, t; }" : "=r"(a) : "l"(p));
    return a;
}
__device__ __forceinline__ void cp16(uint32_t dst, const void* src) {
    asm volatile("cp.async.cg.shared.global [%0], [%1], 16;" :: "r"(dst), "l"(src) : "memory");
}
#define CP_COMMIT() asm volatile("cp.async.commit_group;" ::: "memory")
#define CP_WAIT1()  asm volatile("cp.async.wait_group 1;" ::: "memory")
#define CP_WAIT0()  asm volatile("cp.async.wait_group 0;" ::: "memory")

__device__ __forceinline__ void ldmx4(uint32_t* r, uint32_t addr) {
    asm volatile("ldmatrix.sync.aligned.m8n8.x4.shared.b16 {%0,%1,%2,%3}, [%4];"
                 : "=r"(r[0]), "=r"(r[1]), "=r"(r[2]), "=r"(r[3]) : "r"(addr));
}
__device__ __forceinline__ void mma16816(float* c, const uint32_t* a,
                                         uint32_t b0, uint32_t b1) {
    asm volatile(
        "mma.sync.aligned.m16n8k16.row.col.f32.f16.f16.f32 "
        "{%0,%1,%2,%3}, {%4,%5,%6,%7}, {%8,%9}, {%0,%1,%2,%3};"
        : "+f"(c[0]), "+f"(c[1]), "+f"(c[2]), "+f"(c[3])
        : "r"(a[0]), "r"(a[1]), "r"(a[2]), "r"(a[3]), "r"(b0), "r"(b1));
}
__device__ __forceinline__ void split2(float v0, float v1, __half2& h, __half2& l) {
    __half h0 = __float2half_rn(v0), h1 = __float2half_rn(v1);
    h = __halves2half2(h0, h1);
    l = __halves2half2(__float2half_rn(v0 - __half2float(h0)),
                       __float2half_rn(v1 - __half2float(h1)));
}

// ---------------------------------------------------------------------------
// k_split_x: x fp32 -> xh fp16 (hi only)
// ---------------------------------------------------------------------------
__global__ __launch_bounds__(256) void k_split_x(const float4* __restrict__ x) {
    const size_t idx = (size_t)blockIdx.x * 256 + threadIdx.x;
    float4 v = x[idx];
    __half2 h01 = __halves2half2(__float2half_rn(v.x), __float2half_rn(v.y));
    __half2 h23 = __halves2half2(__float2half_rn(v.z), __float2half_rn(v.w));
    __half2* ph = (__half2*)&g_xh[idx * 4];
    ph[0] = h01; ph[1] = h23;
}

// ---------------------------------------------------------------------------
// k_wprep: u_i = W^T ai, u_j = W^T aj, c_i/c_j; W -> fp16 split. One CTA.
// ---------------------------------------------------------------------------
__global__ __launch_bounds__(256) void k_wprep(const float* __restrict__ W,
                                               const float* __restrict__ bW,
                                               const float* __restrict__ ai,
                                               const float* __restrict__ bi,
                                               const float* __restrict__ aj,
                                               const float* __restrict__ bj) {
    __shared__ float red[16];
    const int v = threadIdx.x;
    float ui = 0.f, uj = 0.f;
    for (int f = 0; f < FD; f++) {
        float w = W[f * VD + v];
        ui += ai[f] * w;
        uj += aj[f] * w;
    }
    g_ui[v] = ui;
    g_uj[v] = uj;

    for (int t = v; t < FD * VD / 2; t += 256) {
        float2 w2 = ((const float2*)W)[t];
        __half2 h, l;
        split2(w2.x, w2.y, h, l);
        *(__half2*)&g_W16h[2 * t] = h;
        *(__half2*)&g_W16l[2 * t] = l;
    }

    float p1 = ai[v] * bW[v];
    float p2 = aj[v] * bW[v];
    const int warp = v >> 5, lane = v & 31;
#pragma unroll
    for (int o = 16; o; o >>= 1) {
        p1 += __shfl_xor_sync(0xFFFFFFFFu, p1, o);
        p2 += __shfl_xor_sync(0xFFFFFFFFu, p2, o);
    }
    if (lane == 0) { red[warp] = p1; red[8 + warp] = p2; }
    __syncthreads();
    if (v == 0) {
        float c1 = bi[0], c2 = bj[0];
        for (int w = 0; w < 8; w++) { c1 += red[w]; c2 += red[8 + w]; }
        g_ci = c1; g_cj = c2;
    }
}

// ---------------------------------------------------------------------------
// k_projx: Wh1/Wh2 directly from x (warp per row)
// ---------------------------------------------------------------------------
__global__ __launch_bounds__(256) void k_projx(const float* __restrict__ x) {
    const int gwarp = (blockIdx.x * blockDim.x + threadIdx.x) >> 5;
    const int lane = threadIdx.x & 31;
    const float* row = x + (size_t)gwarp * VD;
    float s1 = 0.f, s2 = 0.f;
#pragma unroll
    for (int q = 0; q < 8; q++) {
        const int k = lane + 32 * q;
        float v = row[k];
        s1 += v * g_ui[k];
        s2 += v * g_uj[k];
    }
#pragma unroll
    for (int o = 16; o; o >>= 1) {
        s1 += __shfl_xor_sync(0xFFFFFFFFu, s1, o);
        s2 += __shfl_xor_sync(0xFFFFFFFFu, s2, o);
    }
    if (lane == 0) {
        g_Wh1[gwarp] = s1 + g_ci;
        g_Wh2[gwarp] = s2 + g_cj;
    }
}

// ---------------------------------------------------------------------------
// k_bm: adjacency -> bitmask. Warp per HALF row (grid 400) for latency.
// ---------------------------------------------------------------------------
__global__ __launch_bounds__(256) void k_bm(const int* __restrict__ adj) {
    const int wid = threadIdx.x >> 5;
    const int lane = threadIdx.x & 31;
    const int row = blockIdx.x * 4 + (wid >> 1);
    const int w0  = (wid & 1) * 25;
    const int* ar = adj + (size_t)row * NODES;
    for (int w = w0; w < w0 + 25; w++) {
        uint32_t bit = __ballot_sync(0xFFFFFFFFu, ar[w * 32 + lane] > 0);
        if (lane == 0) g_bm[row * 50 + w] = bit;
    }
}

// ---------------------------------------------------------------------------
// k_g1mma: Wh = xh @ W^T (+bW), 2-term (AhBh + AhBl); epilogue -> WhT hi.
// Stage: A 5120 | Bh 10240 @5120 | Bl 10240 @15360
// ---------------------------------------------------------------------------
__global__ __launch_bounds__(256) void k_g1mma(const float* __restrict__ bW) {
    extern __shared__ __align__(128) char dsm[];
    __shared__ float bWs[128];
    const int tid = threadIdx.x, wid = tid >> 5, lane = tid & 31;
    const int m0 = blockIdx.x * 64, n0 = blockIdx.y * 128;
    const int wm = wid >> 2, wn = wid & 3;

    if (tid < 128) bWs[tid] = bW[n0 + tid];

    const __half* Ah = g_xh + (size_t)m0 * VD;
    const __half* Bh = g_W16h + (size_t)n0 * VD;
    const __half* Bl = g_W16l + (size_t)n0 * VD;

    const uint32_t s0 = smem_u32(dsm);

    auto load_chunk = [&](int c) {
        const uint32_t st = s0 + (c & 1) * STAGE_G;
        const int jt = c * KCH;
        {
            int row = tid >> 2, cc = tid & 3;
            uint32_t o = (uint32_t)(row * 80 + cc * 16);
            cp16(st + o, Ah + (size_t)row * VD + jt + cc * 8);
        }
        for (int t = tid; t < 512; t += 256) {
            int row = t >> 2, cc = t & 3;
            uint32_t o = (uint32_t)(row * 80 + cc * 16);
            const size_t go = (size_t)row * VD + jt + cc * 8;
            cp16(st + 5120 + o,  Bh + go);
            cp16(st + 15360 + o, Bl + go);
        }
        CP_COMMIT();
    };

    float acc[2][4][4];
#pragma unroll
    for (int mt = 0; mt < 2; mt++)
#pragma unroll
        for (int nt = 0; nt < 4; nt++)
#pragma unroll
            for (int q = 0; q < 4; q++) acc[mt][nt][q] = 0.f;

    const int aRow = wm * 32 + (lane & 7) + ((lane >> 3) & 1) * 8;
    const int aC16 = ((lane >> 4) & 1) * 16;
    const int bRow = wn * 32 + (lane & 7) + ((lane >> 4) & 1) * 8;
    const int bC16 = ((lane >> 3) & 1) * 16;

    load_chunk(0);

    for (int c = 0; c < NCHG; c++) {
        if (c + 1 < NCHG) { load_chunk(c + 1); CP_WAIT1(); }
        else             { CP_WAIT0(); }
        __syncthreads();
        const uint32_t st = s0 + (c & 1) * STAGE_G;
#pragma unroll
        for (int ks = 0; ks < 2; ks++) {
            const int koff = ks * 32;
            uint32_t ah[2][4], bh[2][4], bl[2][4];
#pragma unroll
            for (int mt = 0; mt < 2; mt++) {
                uint32_t ao = st + (uint32_t)((aRow + mt * 16) * 80 + aC16 + koff);
                ldmx4(ah[mt], ao);
            }
#pragma unroll
            for (int p = 0; p < 2; p++) {
                uint32_t bo = st + 5120 +
                              (uint32_t)((bRow + p * 16) * 80 + bC16 + koff);
                ldmx4(bh[p], bo);
                ldmx4(bl[p], bo + 10240);
            }
#pragma unroll
            for (int mt = 0; mt < 2; mt++) {
#pragma unroll
                for (int nt = 0; nt < 4; nt++) {
                    const int p = nt >> 1, hf = (nt & 1) * 2;
                    mma16816(acc[mt][nt], ah[mt], bh[p][hf], bh[p][hf + 1]);
                    mma16816(acc[mt][nt], ah[mt], bl[p][hf], bl[p][hf + 1]);
                }
            }
        }
        __syncthreads();
    }

    float* s = (float*)dsm;   // [64][129]
#pragma unroll
    for (int mt = 0; mt < 2; mt++) {
        const int ml = wm * 32 + mt * 16 + (lane >> 2);
#pragma unroll
        for (int nt = 0; nt < 4; nt++) {
            const int nl = wn * 32 + nt * 8 + (lane & 3) * 2;
            s[ml * 129 + nl]           = acc[mt][nt][0];
            s[ml * 129 + nl + 1]       = acc[mt][nt][1];
            s[(ml + 8) * 129 + nl]     = acc[mt][nt][2];
            s[(ml + 8) * 129 + nl + 1] = acc[mt][nt][3];
        }
    }
    __syncthreads();

    const int b  = m0 / NODES;
    const int j0 = m0 % NODES;
#pragma unroll
    for (int it = 0; it < 16; it++) {
        const int f = wid * 16 + it;
        const float bw = bWs[f];
        float v0 = s[(2 * lane) * 129 + f] + bw;
        float v1 = s[(2 * lane + 1) * 129 + f] + bw;
        __half2 h = __halves2half2(__float2half_rn(v0), __float2half_rn(v1));
        size_t o = ((size_t)(b * FD + n0 + f)) * NODES + j0 + 2 * lane;
        *(__half2*)&g_WhT_hi[o] = h;
    }
}

// ---------------------------------------------------------------------------
// k_mma2f: FUSED masked-softmax + P @ Wh^T + deferred norm + ELU.
// Triple-buffered A and B -> ONE __syncthreads per chunk, prefetch preserved.
// ---------------------------------------------------------------------------
__global__ __launch_bounds__(256) void k_mma2f(float* __restrict__ out) {
    extern __shared__ __align__(128) char dsm[];
    float*    Wh2s = (float*)dsm;                 // 1600 @ 0
    float*    wh1s = Wh2s + NODES;                // 64   @ 6400
    float*    ms   = wh1s + 64;                   // 64   @ 6656
    float*    rows = ms + 64;                     // 64   @ 6912
    uint32_t* bms  = (uint32_t*)(rows + 64);      // 64*50 @ 7168

    const int tid = threadIdx.x, wid = tid >> 5, lane = tid & 31;
    const int m0 = blockIdx.x * 64, n0 = blockIdx.y * 128, b = blockIdx.z;
    const int wm = wid >> 2, wn = wid & 3;

    const __half* Bh = g_WhT_hi + ((size_t)b * FD + n0) * NODES;

    const uint32_t s0 = smem_u32(dsm);
    const uint32_t sA = s0 + ABASE;
    const uint32_t sB = s0 + BBASE;

    auto loadB = [&](int c) {
        const uint32_t st = sB + (uint32_t)(c % 3) * 10240;
        const int jt = c * KCH;
        for (int t = tid; t < 512; t += 256) {
            int row = t >> 2, cc = t & 3;
            uint32_t o = (uint32_t)(row * 80 + cc * 16);
            cp16(st + o, Bh + (size_t)row * NODES + jt + cc * 8);
        }
        CP_COMMIT();
    };

    loadB(0);

    // ---- fill smem: Wh2 row, Wh1 tile, bitmask rows ----
    for (int j = tid; j < NODES; j += 256)
        Wh2s[j] = g_Wh2[b * NODES + j];
    if (tid < 64)
        wh1s[tid] = g_Wh1[b * NODES + m0 + tid];
    for (int t = tid; t < 64 * 50; t += 256)
        bms[t] = g_bm[m0 * 50 + t];
    __syncthreads();

    // ---- prologue: masked max per row (warp wid -> rows wid*8..wid*8+7) ----
#pragma unroll
    for (int rr = 0; rr < 8; rr++) {
        const int r = wid * 8 + rr;
        const uint32_t* bmr = &bms[r * 50];
        float mx = -3e38f;
        for (int w = 0; w < 50; w++)
            if ((bmr[w] >> lane) & 1) mx = fmaxf(mx, Wh2s[w * 32 + lane]);
#pragma unroll
        for (int o = 16; o; o >>= 1) mx = fmaxf(mx, __shfl_xor_sync(0xFFFFFFFFu, mx, o));
        if (lane == 0) {
            float em = wh1s[r] + mx;
            em = em > 0.f ? em : 0.2f * em;
            ms[r] = (mx > -1e30f) ? em : -1e9f;
        }
    }
    __syncthreads();

    float acc[2][4][4];
#pragma unroll
    for (int mt = 0; mt < 2; mt++)
#pragma unroll
        for (int nt = 0; nt < 4; nt++)
#pragma unroll
            for (int q = 0; q < 4; q++) acc[mt][nt][q] = 0.f;

    const int aRow = wm * 32 + (lane & 7) + ((lane >> 3) & 1) * 8;
    const int aC16 = ((lane >> 4) & 1) * 16;
    const int bRow = wn * 32 + (lane & 7) + ((lane >> 4) & 1) * 8;
    const int bC16 = ((lane >> 3) & 1) * 16;

    // P-tile compute mapping: thread -> row pr (0..63), col group pq (0..3)
    const int pr = tid >> 2, pq = tid & 3;
    const float wh1r = wh1s[pr];
    const float mr   = ms[pr];
    const uint32_t* bmp = &bms[pr * 50];
    float sacc = 0.f;   // partial row sum of ROUNDED P

    auto computeA = [&](int c) {
        const int jt = c * KCH;
        const uint32_t word = bmp[c];
        uint32_t uv[4];
#pragma unroll
        for (int u = 0; u < 4; u++) {
            const int jj = pq * 8 + u * 2;
            float2 w2 = *(const float2*)&Wh2s[jt + jj];
            float e0 = wh1r + w2.x; e0 = e0 > 0.f ? e0 : 0.2f * e0;
            float e1 = wh1r + w2.y; e1 = e1 > 0.f ? e1 : 0.2f * e1;
            float x0 = __expf((((word >> jj) & 1)       ? e0 : -1e9f) - mr);
            float x1 = __expf((((word >> (jj + 1)) & 1) ? e1 : -1e9f) - mr);
            __half2 hh = __halves2half2(__float2half_rn(x0), __float2half_rn(x1));
            uv[u] = *(uint32_t*)&hh;
            sacc += __low2float(hh) + __high2float(hh);
        }
        *(uint4*)(dsm + ABASE + (size_t)(c % 3) * 5120 + pr * 80 + pq * 16) =
            make_uint4(uv[0], uv[1], uv[2], uv[3]);
    };

    computeA(0);   // A(0); visible after X(0)

    for (int c = 0; c < NCH; c++) {
        // prefetch head start: issue B(c+1) BEFORE waiting for B(c).
        // Triple buffers make this safe with a single barrier per chunk:
        // buf (c+1)%3's last readers ran in chunk c-2, before X(c-1).
        if (c + 1 < NCH) { loadB(c + 1); CP_WAIT1(); }
        else             { CP_WAIT0(); }
        __syncthreads();     // X(c): A(c)+B(c) published

        const uint32_t stA = sA + (uint32_t)(c % 3) * 5120;
        const uint32_t stB = sB + (uint32_t)(c % 3) * 10240;
#pragma unroll
        for (int ks = 0; ks < 2; ks++) {
            const int koff = ks * 32;
            uint32_t ah[2][4], bh[2][4];
#pragma unroll
            for (int mt = 0; mt < 2; mt++) {
                uint32_t ao = stA + (uint32_t)((aRow + mt * 16) * 80 + aC16 + koff);
                ldmx4(ah[mt], ao);
            }
#pragma unroll
            for (int p = 0; p < 2; p++) {
                uint32_t bo = stB + (uint32_t)((bRow + p * 16) * 80 + bC16 + koff);
                ldmx4(bh[p], bo);
            }
#pragma unroll
            for (int mt = 0; mt < 2; mt++) {
#pragma unroll
                for (int nt = 0; nt < 4; nt++) {
                    const int p = nt >> 1, hf = (nt & 1) * 2;
                    mma16816(acc[mt][nt], ah[mt], bh[p][hf], bh[p][hf + 1]);
                }
            }
        }

        // exp work for chunk c+1 overlaps chunk-c HMMA drain (A buf (c+1)%3)
        if (c + 1 < NCH) computeA(c + 1);
    }

    // ---- publish row sums (reduce across the 4 pq lanes of each row) ----
    sacc += __shfl_xor_sync(0xFFFFFFFFu, sacc, 1);
    sacc += __shfl_xor_sync(0xFFFFFFFFu, sacc, 2);
    __syncthreads();
    if (pq == 0) rows[pr] = sacc;
    __syncthreads();

    // ---- epilogue: scale by 1/rowsum, ELU, store ----
#pragma unroll
    for (int mt = 0; mt < 2; mt++) {
        const int ml = wm * 32 + mt * 16 + (lane >> 2);
        const int mA = m0 + ml;
        const float ilA = 1.f / rows[ml];
        const float ilB = 1.f / rows[ml + 8];
#pragma unroll
        for (int nt = 0; nt < 4; nt++) {
            const int n = n0 + wn * 32 + nt * 8 + (lane & 3) * 2;
            float* op = out + ((size_t)(b * NODES) + mA) * FD + n;
            float d0 = acc[mt][nt][0] * ilA, d1 = acc[mt][nt][1] * ilA;
            float d2 = acc[mt][nt][2] * ilB, d3 = acc[mt][nt][3] * ilB;
            float2 v0, v1;
            v0.x = d0 > 0.f ? d0 : (__expf(d0) - 1.f);
            v0.y = d1 > 0.f ? d1 : (__expf(d1) - 1.f);
            v1.x = d2 > 0.f ? d2 : (__expf(d2) - 1.f);
            v1.y = d3 > 0.f ? d3 : (__expf(d3) - 1.f);
            *(float2*)op = v0;
            *(float2*)(op + 8 * FD) = v1;
        }
    }
}

// ---------------------------------------------------------------------------
extern "C" void kernel_launch(void* const* d_in, const int* in_sizes, int n_in,
                              void* d_out, int out_size) {
    const float* h   = (const float*)d_in[0];
    const int*   adj = (const int*)  d_in[1];
    const float* W   = (const float*)d_in[2];
    const float* bW  = (const float*)d_in[3];
    const float* ai  = (const float*)d_in[4];
    const float* bi  = (const float*)d_in[5];
    const float* aj  = (const float*)d_in[6];
    const float* bj  = (const float*)d_in[7];
    float* out = (float*)d_out;

    cudaFuncSetAttribute(k_g1mma, cudaFuncAttributeMaxDynamicSharedMemorySize, SMEM_G);
    cudaFuncSetAttribute(k_mma2f, cudaFuncAttributeMaxDynamicSharedMemorySize, SMEM_M);

    k_split_x<<<(MTOT * VD / 4) / 256, 256>>>((const float4*)h);
    k_wprep<<<1, 256>>>(W, bW, ai, bi, aj, bj);
    k_projx<<<MTOT / 8, 256>>>(h);
    k_bm<<<NODES / 4, 256>>>(adj);
    k_g1mma<<<dim3(MTOT / 64, 2), 256, SMEM_G>>>(bW);
    dim3 gm(NODES / 64, FD / 128, BB);
    k_mma2f<<<gm, 256, SMEM_M>>>(out);
}

// round 14
// speedup vs baseline: 1.6229x; 1.0941x over previous
#include <cuda_runtime.h>
#include <cuda_fp16.h>
#include <cstdint>

#define BB      8
#define NODES   1600
#define VD      256
#define FD      256
#define MTOT    (BB * NODES)   // 12800
#define KCH     32
#define NCH     (NODES / KCH)  // 50  (k_mma2f)
#define NCHG    (VD / KCH)     // 8   (k_g1mma)
// k_g1mma stages (A hi + B hi); epilogue reuses smem as float[64][129]=33024B,
// which exceeds 2*STAGE_G -> allocation must cover BOTH uses.
#define STAGE_G 15360
#define SMEM_G  33024
// k_mma2f smem: header 19968 | A x3 @ ABASE | B x3 @ BBASE
#define ABASE   19968
#define BBASE   (ABASE + 3 * 5120)      // 35328
#define SMEM_M  (BBASE + 3 * 10240)     // 66048

// ---------------- scratch (device globals; allocation-free) ----------------
__device__ float                 g_Wh1 [MTOT];
__device__ float                 g_Wh2 [MTOT];
__device__ float                 g_ui[VD], g_uj[VD];
__device__ float                 g_ci, g_cj;
__device__ uint32_t              g_bm[NODES * 50];
__device__ __align__(128) __half g_xh[(size_t)MTOT * VD];
__device__ __align__(128) __half g_W16h[FD * VD];
__device__ __align__(128) __half g_WhT_hi[BB * FD * NODES];

// ---------------- PTX helpers (sm_80-era only) ----------------
__device__ __forceinline__ uint32_t smem_u32(const void* p) {
    uint32_t a;
    asm("{ .reg .u64 t; cvta.to.shared.u64 t, %1; cvt.u32.u64 %0, t; }" : "=r"(a) : "l"(p));
    return a;
}
__device__ __forceinline__ void cp16(uint32_t dst, const void* src) {
    asm volatile("cp.async.cg.shared.global [%0], [%1], 16;" :: "r"(dst), "l"(src) : "memory");
}
#define CP_COMMIT() asm volatile("cp.async.commit_group;" ::: "memory")
#define CP_WAIT1()  asm volatile("cp.async.wait_group 1;" ::: "memory")
#define CP_WAIT0()  asm volatile("cp.async.wait_group 0;" ::: "memory")

__device__ __forceinline__ void ldmx4(uint32_t* r, uint32_t addr) {
    asm volatile("ldmatrix.sync.aligned.m8n8.x4.shared.b16 {%0,%1,%2,%3}, [%4];"
                 : "=r"(r[0]), "=r"(r[1]), "=r"(r[2]), "=r"(r[3]) : "r"(addr));
}
__device__ __forceinline__ void mma16816(float* c, const uint32_t* a,
                                         uint32_t b0, uint32_t b1) {
    asm volatile(
        "mma.sync.aligned.m16n8k16.row.col.f32.f16.f16.f32 "
        "{%0,%1,%2,%3}, {%4,%5,%6,%7}, {%8,%9}, {%0,%1,%2,%3};"
        : "+f"(c[0]), "+f"(c[1]), "+f"(c[2]), "+f"(c[3])
        : "r"(a[0]), "r"(a[1]), "r"(a[2]), "r"(a[3]), "r"(b0), "r"(b1));
}

// ---------------------------------------------------------------------------
// k_wprep: u_i = W^T ai, u_j = W^T aj, c_i/c_j; W -> fp16 (hi only). One CTA.
// ---------------------------------------------------------------------------
__global__ __launch_bounds__(256) void k_wprep(const float* __restrict__ W,
                                               const float* __restrict__ bW,
                                               const float* __restrict__ ai,
                                               const float* __restrict__ bi,
                                               const float* __restrict__ aj,
                                               const float* __restrict__ bj) {
    __shared__ float red[16];
    const int v = threadIdx.x;
    float ui = 0.f, uj = 0.f;
    for (int f = 0; f < FD; f++) {
        float w = W[f * VD + v];
        ui += ai[f] * w;
        uj += aj[f] * w;
    }
    g_ui[v] = ui;
    g_uj[v] = uj;

    for (int t = v; t < FD * VD / 2; t += 256) {
        float2 w2 = ((const float2*)W)[t];
        *(__half2*)&g_W16h[2 * t] =
            __halves2half2(__float2half_rn(w2.x), __float2half_rn(w2.y));
    }

    float p1 = ai[v] * bW[v];
    float p2 = aj[v] * bW[v];
    const int warp = v >> 5, lane = v & 31;
#pragma unroll
    for (int o = 16; o; o >>= 1) {
        p1 += __shfl_xor_sync(0xFFFFFFFFu, p1, o);
        p2 += __shfl_xor_sync(0xFFFFFFFFu, p2, o);
    }
    if (lane == 0) { red[warp] = p1; red[8 + warp] = p2; }
    __syncthreads();
    if (v == 0) {
        float c1 = bi[0], c2 = bj[0];
        for (int w = 0; w < 8; w++) { c1 += red[w]; c2 += red[8 + w]; }
        g_ci = c1; g_cj = c2;
    }
}

// ---------------------------------------------------------------------------
// k_prep_x: ONE pass over x -> xh (fp16) + Wh1/Wh2 projections. Warp per row.
// ---------------------------------------------------------------------------
__global__ __launch_bounds__(256) void k_prep_x(const float2* __restrict__ x2) {
    const int row = (blockIdx.x * blockDim.x + threadIdx.x) >> 5;   // 12800 rows
    const int lane = threadIdx.x & 31;
    const float2* xr = x2 + (size_t)row * 128;
    __half2* xo = (__half2*)g_xh + (size_t)row * 128;
    float s1 = 0.f, s2 = 0.f;
#pragma unroll
    for (int q = 0; q < 4; q++) {
        const int k = lane + 32 * q;          // float2 index (2 elements)
        float2 v = xr[k];
        float2 u = ((const float2*)g_ui)[k];
        float2 w = ((const float2*)g_uj)[k];
        s1 += v.x * u.x + v.y * u.y;
        s2 += v.x * w.x + v.y * w.y;
        xo[k] = __halves2half2(__float2half_rn(v.x), __float2half_rn(v.y));
    }
#pragma unroll
    for (int o = 16; o; o >>= 1) {
        s1 += __shfl_xor_sync(0xFFFFFFFFu, s1, o);
        s2 += __shfl_xor_sync(0xFFFFFFFFu, s2, o);
    }
    if (lane == 0) {
        g_Wh1[row] = s1 + g_ci;
        g_Wh2[row] = s2 + g_cj;
    }
}

// ---------------------------------------------------------------------------
// k_bm: adjacency -> bitmask. Warp per half-row; loads batched (MLP=10/5).
// ---------------------------------------------------------------------------
__global__ __launch_bounds__(256) void k_bm(const int* __restrict__ adj) {
    const int wid = threadIdx.x >> 5;
    const int lane = threadIdx.x & 31;
    const int row = blockIdx.x * 4 + (wid >> 1);
    const int w0  = (wid & 1) * 25;
    const int* ar = adj + (size_t)row * NODES + w0 * 32 + lane;
#pragma unroll
    for (int bch = 0; bch < 3; bch++) {
        int a[10];
        const int nb = (bch == 2) ? 5 : 10;
#pragma unroll
        for (int k = 0; k < 10; k++)
            if (k < nb) a[k] = ar[(bch * 10 + k) * 32];
#pragma unroll
        for (int k = 0; k < 10; k++) {
            if (k < nb) {
                uint32_t bit = __ballot_sync(0xFFFFFFFFu, a[k] > 0);
                if (lane == 0) g_bm[row * 50 + w0 + bch * 10 + k] = bit;
            }
        }
    }
}

// ---------------------------------------------------------------------------
// k_g1mma: Wh = xh @ W16h^T (+bW), single-term; epilogue -> WhT hi.
// Stage: A 5120 | Bh 10240 @5120
// ---------------------------------------------------------------------------
__global__ __launch_bounds__(256) void k_g1mma(const float* __restrict__ bW) {
    extern __shared__ __align__(128) char dsm[];
    __shared__ float bWs[128];
    const int tid = threadIdx.x, wid = tid >> 5, lane = tid & 31;
    const int m0 = blockIdx.x * 64, n0 = blockIdx.y * 128;
    const int wm = wid >> 2, wn = wid & 3;

    if (tid < 128) bWs[tid] = bW[n0 + tid];

    const __half* Ah = g_xh + (size_t)m0 * VD;
    const __half* Bh = g_W16h + (size_t)n0 * VD;

    const uint32_t s0 = smem_u32(dsm);

    auto load_chunk = [&](int c) {
        const uint32_t st = s0 + (c & 1) * STAGE_G;
        const int jt = c * KCH;
        {
            int row = tid >> 2, cc = tid & 3;
            uint32_t o = (uint32_t)(row * 80 + cc * 16);
            cp16(st + o, Ah + (size_t)row * VD + jt + cc * 8);
        }
        for (int t = tid; t < 512; t += 256) {
            int row = t >> 2, cc = t & 3;
            uint32_t o = (uint32_t)(row * 80 + cc * 16);
            cp16(st + 5120 + o, Bh + (size_t)row * VD + jt + cc * 8);
        }
        CP_COMMIT();
    };

    float acc[2][4][4];
#pragma unroll
    for (int mt = 0; mt < 2; mt++)
#pragma unroll
        for (int nt = 0; nt < 4; nt++)
#pragma unroll
            for (int q = 0; q < 4; q++) acc[mt][nt][q] = 0.f;

    const int aRow = wm * 32 + (lane & 7) + ((lane >> 3) & 1) * 8;
    const int aC16 = ((lane >> 4) & 1) * 16;
    const int bRow = wn * 32 + (lane & 7) + ((lane >> 4) & 1) * 8;
    const int bC16 = ((lane >> 3) & 1) * 16;

    load_chunk(0);

    for (int c = 0; c < NCHG; c++) {
        if (c + 1 < NCHG) { load_chunk(c + 1); CP_WAIT1(); }
        else             { CP_WAIT0(); }
        __syncthreads();
        const uint32_t st = s0 + (c & 1) * STAGE_G;
#pragma unroll
        for (int ks = 0; ks < 2; ks++) {
            const int koff = ks * 32;
            uint32_t ah[2][4], bh[2][4];
#pragma unroll
            for (int mt = 0; mt < 2; mt++) {
                uint32_t ao = st + (uint32_t)((aRow + mt * 16) * 80 + aC16 + koff);
                ldmx4(ah[mt], ao);
            }
#pragma unroll
            for (int p = 0; p < 2; p++) {
                uint32_t bo = st + 5120 +
                              (uint32_t)((bRow + p * 16) * 80 + bC16 + koff);
                ldmx4(bh[p], bo);
            }
#pragma unroll
            for (int mt = 0; mt < 2; mt++) {
#pragma unroll
                for (int nt = 0; nt < 4; nt++) {
                    const int p = nt >> 1, hf = (nt & 1) * 2;
                    mma16816(acc[mt][nt], ah[mt], bh[p][hf], bh[p][hf + 1]);
                }
            }
        }
        __syncthreads();
    }

    float* s = (float*)dsm;   // [64][129] = 33024 B (covered by SMEM_G)
#pragma unroll
    for (int mt = 0; mt < 2; mt++) {
        const int ml = wm * 32 + mt * 16 + (lane >> 2);
#pragma unroll
        for (int nt = 0; nt < 4; nt++) {
            const int nl = wn * 32 + nt * 8 + (lane & 3) * 2;
            s[ml * 129 + nl]           = acc[mt][nt][0];
            s[ml * 129 + nl + 1]       = acc[mt][nt][1];
            s[(ml + 8) * 129 + nl]     = acc[mt][nt][2];
            s[(ml + 8) * 129 + nl + 1] = acc[mt][nt][3];
        }
    }
    __syncthreads();

    const int b  = m0 / NODES;
    const int j0 = m0 % NODES;
#pragma unroll
    for (int it = 0; it < 16; it++) {
        const int f = wid * 16 + it;
        const float bw = bWs[f];
        float v0 = s[(2 * lane) * 129 + f] + bw;
        float v1 = s[(2 * lane + 1) * 129 + f] + bw;
        __half2 h = __halves2half2(__float2half_rn(v0), __float2half_rn(v1));
        size_t o = ((size_t)(b * FD + n0 + f)) * NODES + j0 + 2 * lane;
        *(__half2*)&g_WhT_hi[o] = h;
    }
}

// ---------------------------------------------------------------------------
// k_mma2f: FUSED masked-softmax + P @ Wh^T + deferred norm + ELU.
// Triple-buffered A and B -> ONE __syncthreads per chunk, prefetch preserved.
// ---------------------------------------------------------------------------
__global__ __launch_bounds__(256) void k_mma2f(float* __restrict__ out) {
    extern __shared__ __align__(128) char dsm[];
    float*    Wh2s = (float*)dsm;                 // 1600 @ 0
    float*    wh1s = Wh2s + NODES;                // 64   @ 6400
    float*    ms   = wh1s + 64;                   // 64   @ 6656
    float*    rows = ms + 64;                     // 64   @ 6912
    uint32_t* bms  = (uint32_t*)(rows + 64);      // 64*50 @ 7168

    const int tid = threadIdx.x, wid = tid >> 5, lane = tid & 31;
    const int m0 = blockIdx.x * 64, n0 = blockIdx.y * 128, b = blockIdx.z;
    const int wm = wid >> 2, wn = wid & 3;

    const __half* Bh = g_WhT_hi + ((size_t)b * FD + n0) * NODES;

    const uint32_t s0 = smem_u32(dsm);
    const uint32_t sA = s0 + ABASE;
    const uint32_t sB = s0 + BBASE;

    auto loadB = [&](int c) {
        const uint32_t st = sB + (uint32_t)(c % 3) * 10240;
        const int jt = c * KCH;
        for (int t = tid; t < 512; t += 256) {
            int row = t >> 2, cc = t & 3;
            uint32_t o = (uint32_t)(row * 80 + cc * 16);
            cp16(st + o, Bh + (size_t)row * NODES + jt + cc * 8);
        }
        CP_COMMIT();
    };

    loadB(0);

    // ---- fill smem: Wh2 row, Wh1 tile, bitmask rows ----
    for (int j = tid; j < NODES; j += 256)
        Wh2s[j] = g_Wh2[b * NODES + j];
    if (tid < 64)
        wh1s[tid] = g_Wh1[b * NODES + m0 + tid];
    for (int t = tid; t < 64 * 50; t += 256)
        bms[t] = g_bm[m0 * 50 + t];
    __syncthreads();

    // ---- prologue: masked max per row (warp wid -> rows wid*8..wid*8+7) ----
#pragma unroll
    for (int rr = 0; rr < 8; rr++) {
        const int r = wid * 8 + rr;
        const uint32_t* bmr = &bms[r * 50];
        float mx = -3e38f;
        for (int w = 0; w < 50; w++)
            if ((bmr[w] >> lane) & 1) mx = fmaxf(mx, Wh2s[w * 32 + lane]);
#pragma unroll
        for (int o = 16; o; o >>= 1) mx = fmaxf(mx, __shfl_xor_sync(0xFFFFFFFFu, mx, o));
        if (lane == 0) {
            float em = wh1s[r] + mx;
            em = em > 0.f ? em : 0.2f * em;
            ms[r] = (mx > -1e30f) ? em : -1e9f;
        }
    }
    __syncthreads();

    float acc[2][4][4];
#pragma unroll
    for (int mt = 0; mt < 2; mt++)
#pragma unroll
        for (int nt = 0; nt < 4; nt++)
#pragma unroll
            for (int q = 0; q < 4; q++) acc[mt][nt][q] = 0.f;

    const int aRow = wm * 32 + (lane & 7) + ((lane >> 3) & 1) * 8;
    const int aC16 = ((lane >> 4) & 1) * 16;
    const int bRow = wn * 32 + (lane & 7) + ((lane >> 4) & 1) * 8;
    const int bC16 = ((lane >> 3) & 1) * 16;

    // P-tile compute mapping: thread -> row pr (0..63), col group pq (0..3)
    const int pr = tid >> 2, pq = tid & 3;
    const float wh1r = wh1s[pr];
    const float mr   = ms[pr];
    const uint32_t* bmp = &bms[pr * 50];
    float sacc = 0.f;   // partial row sum of ROUNDED P

    auto computeA = [&](int c) {
        const int jt = c * KCH;
        const uint32_t word = bmp[c];
        uint32_t uv[4];
#pragma unroll
        for (int u = 0; u < 4; u++) {
            const int jj = pq * 8 + u * 2;
            float2 w2 = *(const float2*)&Wh2s[jt + jj];
            float e0 = wh1r + w2.x; e0 = e0 > 0.f ? e0 : 0.2f * e0;
            float e1 = wh1r + w2.y; e1 = e1 > 0.f ? e1 : 0.2f * e1;
            float x0 = __expf((((word >> jj) & 1)       ? e0 : -1e9f) - mr);
            float x1 = __expf((((word >> (jj + 1)) & 1) ? e1 : -1e9f) - mr);
            __half2 hh = __halves2half2(__float2half_rn(x0), __float2half_rn(x1));
            uv[u] = *(uint32_t*)&hh;
            sacc += __low2float(hh) + __high2float(hh);
        }
        *(uint4*)(dsm + ABASE + (size_t)(c % 3) * 5120 + pr * 80 + pq * 16) =
            make_uint4(uv[0], uv[1], uv[2], uv[3]);
    };

    computeA(0);   // A(0); visible after X(0)

    for (int c = 0; c < NCH; c++) {
        // prefetch head start: issue B(c+1) BEFORE waiting for B(c).
        if (c + 1 < NCH) { loadB(c + 1); CP_WAIT1(); }
        else             { CP_WAIT0(); }
        __syncthreads();     // X(c): A(c)+B(c) published

        const uint32_t stA = sA + (uint32_t)(c % 3) * 5120;
        const uint32_t stB = sB + (uint32_t)(c % 3) * 10240;
#pragma unroll
        for (int ks = 0; ks < 2; ks++) {
            const int koff = ks * 32;
            uint32_t ah[2][4], bh[2][4];
#pragma unroll
            for (int mt = 0; mt < 2; mt++) {
                uint32_t ao = stA + (uint32_t)((aRow + mt * 16) * 80 + aC16 + koff);
                ldmx4(ah[mt], ao);
            }
#pragma unroll
            for (int p = 0; p < 2; p++) {
                uint32_t bo = stB + (uint32_t)((bRow + p * 16) * 80 + bC16 + koff);
                ldmx4(bh[p], bo);
            }
#pragma unroll
            for (int mt = 0; mt < 2; mt++) {
#pragma unroll
                for (int nt = 0; nt < 4; nt++) {
                    const int p = nt >> 1, hf = (nt & 1) * 2;
                    mma16816(acc[mt][nt], ah[mt], bh[p][hf], bh[p][hf + 1]);
                }
            }
        }

        // exp work for chunk c+1 overlaps chunk-c HMMA drain (A buf (c+1)%3)
        if (c + 1 < NCH) computeA(c + 1);
    }

    // ---- publish row sums (reduce across the 4 pq lanes of each row) ----
    sacc += __shfl_xor_sync(0xFFFFFFFFu, sacc, 1);
    sacc += __shfl_xor_sync(0xFFFFFFFFu, sacc, 2);
    __syncthreads();
    if (pq == 0) rows[pr] = sacc;
    __syncthreads();

    // ---- epilogue: scale by 1/rowsum, ELU, store ----
#pragma unroll
    for (int mt = 0; mt < 2; mt++) {
        const int ml = wm * 32 + mt * 16 + (lane >> 2);
        const int mA = m0 + ml;
        const float ilA = 1.f / rows[ml];
        const float ilB = 1.f / rows[ml + 8];
#pragma unroll
        for (int nt = 0; nt < 4; nt++) {
            const int n = n0 + wn * 32 + nt * 8 + (lane & 3) * 2;
            float* op = out + ((size_t)(b * NODES) + mA) * FD + n;
            float d0 = acc[mt][nt][0] * ilA, d1 = acc[mt][nt][1] * ilA;
            float d2 = acc[mt][nt][2] * ilB, d3 = acc[mt][nt][3] * ilB;
            float2 v0, v1;
            v0.x = d0 > 0.f ? d0 : (__expf(d0) - 1.f);
            v0.y = d1 > 0.f ? d1 : (__expf(d1) - 1.f);
            v1.x = d2 > 0.f ? d2 : (__expf(d2) - 1.f);
            v1.y = d3 > 0.f ? d3 : (__expf(d3) - 1.f);
            *(float2*)op = v0;
            *(float2*)(op + 8 * FD) = v1;
        }
    }
}

// ---------------------------------------------------------------------------
extern "C" void kernel_launch(void* const* d_in, const int* in_sizes, int n_in,
                              void* d_out, int out_size) {
    const float* h   = (const float*)d_in[0];
    const int*   adj = (const int*)  d_in[1];
    const float* W   = (const float*)d_in[2];
    const float* bW  = (const float*)d_in[3];
    const float* ai  = (const float*)d_in[4];
    const float* bi  = (const float*)d_in[5];
    const float* aj  = (const float*)d_in[6];
    const float* bj  = (const float*)d_in[7];
    float* out = (float*)d_out;

    cudaFuncSetAttribute(k_g1mma, cudaFuncAttributeMaxDynamicSharedMemorySize, SMEM_G);
    cudaFuncSetAttribute(k_mma2f, cudaFuncAttributeMaxDynamicSharedMemorySize, SMEM_M);

    k_wprep<<<1, 256>>>(W, bW, ai, bi, aj, bj);
    k_prep_x<<<(MTOT * 32) / 256, 256>>>((const float2*)h);
    k_bm<<<NODES / 4, 256>>>(adj);
    k_g1mma<<<dim3(MTOT / 64, 2), 256, SMEM_G>>>(bW);
    dim3 gm(NODES / 64, FD / 128, BB);
    k_mma2f<<<gm, 256, SMEM_M>>>(out);
}

// round 15
// speedup vs baseline: 1.6800x; 1.0352x over previous
#include <cuda_runtime.h>
#include <cuda_fp16.h>
#include <cstdint>

#define BB      8
#define NODES   1600
#define VD      256
#define FD      256
#define MTOT    (BB * NODES)   // 12800
#define KCH     32
#define NCH     (NODES / KCH)  // 50  (k_mma2f)
#define NCHG    (VD / KCH)     // 8   (k_g1mma)
// k_g1mma: 4 stages (A hi + B hi); epilogue reuses smem as float[64][129]=33024B
#define STAGE_G 15360
#define SMEM_G  (4 * STAGE_G)           // 61440 >= 33024
// k_mma2f smem map (bytes):
// Wh2s 0..6400 | wh1s ..6656 | ms ..6912 | rows ..7168 | red ..7200 |
// bms ..20000 | E1h ..23200 | E2h ..26400 | A x3 @26400 | B x3 @41760
#define ABASE   26400
#define BBASE   (ABASE + 3 * 5120)      // 41760
#define SMEM_M  (BBASE + 3 * 10240)     // 72480 (x3 = 217440 <= smem/SM)

// ---------------- scratch (device globals; allocation-free) ----------------
__device__ float                 g_Wh1 [MTOT];
__device__ float                 g_Wh2 [MTOT];
__device__ float                 g_ui[VD], g_uj[VD];
__device__ float                 g_ci, g_cj;
__device__ uint32_t              g_bm[NODES * 50];
__device__ __align__(128) __half g_xh[(size_t)MTOT * VD];
__device__ __align__(128) __half g_W16h[FD * VD];
__device__ __align__(128) __half g_WhT_hi[BB * FD * NODES];

// ---------------- PTX helpers (sm_80-era only) ----------------
__device__ __forceinline__ uint32_t smem_u32(const void* p) {
    uint32_t a;
    asm("{ .reg .u64 t; cvta.to.shared.u64 t, %1; cvt.u32.u64 %0, t; }" : "=r"(a) : "l"(p));
    return a;
}
__device__ __forceinline__ void cp16(uint32_t dst, const void* src) {
    asm volatile("cp.async.cg.shared.global [%0], [%1], 16;" :: "r"(dst), "l"(src) : "memory");
}
#define CP_COMMIT() asm volatile("cp.async.commit_group;" ::: "memory")
#define CP_WAIT3()  asm volatile("cp.async.wait_group 3;" ::: "memory")
#define CP_WAIT2()  asm volatile("cp.async.wait_group 2;" ::: "memory")
#define CP_WAIT1()  asm volatile("cp.async.wait_group 1;" ::: "memory")
#define CP_WAIT0()  asm volatile("cp.async.wait_group 0;" ::: "memory")

__device__ __forceinline__ void ldmx4(uint32_t* r, uint32_t addr) {
    asm volatile("ldmatrix.sync.aligned.m8n8.x4.shared.b16 {%0,%1,%2,%3}, [%4];"
                 : "=r"(r[0]), "=r"(r[1]), "=r"(r[2]), "=r"(r[3]) : "r"(addr));
}
__device__ __forceinline__ void mma16816(float* c, const uint32_t* a,
                                         uint32_t b0, uint32_t b1) {
    asm volatile(
        "mma.sync.aligned.m16n8k16.row.col.f32.f16.f16.f32 "
        "{%0,%1,%2,%3}, {%4,%5,%6,%7}, {%8,%9}, {%0,%1,%2,%3};"
        : "+f"(c[0]), "+f"(c[1]), "+f"(c[2]), "+f"(c[3])
        : "r"(a[0]), "r"(a[1]), "r"(a[2]), "r"(a[3]), "r"(b0), "r"(b1));
}

// ---------------------------------------------------------------------------
// k_wprep: u_i = W^T ai, u_j = W^T aj, c_i/c_j; W -> fp16 (hi only). One CTA.
// ---------------------------------------------------------------------------
__global__ __launch_bounds__(256) void k_wprep(const float* __restrict__ W,
                                               const float* __restrict__ bW,
                                               const float* __restrict__ ai,
                                               const float* __restrict__ bi,
                                               const float* __restrict__ aj,
                                               const float* __restrict__ bj) {
    __shared__ float red[16];
    const int v = threadIdx.x;
    float ui = 0.f, uj = 0.f;
    for (int f = 0; f < FD; f++) {
        float w = W[f * VD + v];
        ui += ai[f] * w;
        uj += aj[f] * w;
    }
    g_ui[v] = ui;
    g_uj[v] = uj;

    for (int t = v; t < FD * VD / 2; t += 256) {
        float2 w2 = ((const float2*)W)[t];
        *(__half2*)&g_W16h[2 * t] =
            __halves2half2(__float2half_rn(w2.x), __float2half_rn(w2.y));
    }

    float p1 = ai[v] * bW[v];
    float p2 = aj[v] * bW[v];
    const int warp = v >> 5, lane = v & 31;
#pragma unroll
    for (int o = 16; o; o >>= 1) {
        p1 += __shfl_xor_sync(0xFFFFFFFFu, p1, o);
        p2 += __shfl_xor_sync(0xFFFFFFFFu, p2, o);
    }
    if (lane == 0) { red[warp] = p1; red[8 + warp] = p2; }
    __syncthreads();
    if (v == 0) {
        float c1 = bi[0], c2 = bj[0];
        for (int w = 0; w < 8; w++) { c1 += red[w]; c2 += red[8 + w]; }
        g_ci = c1; g_cj = c2;
    }
}

// ---------------------------------------------------------------------------
// k_prep_x: ONE pass over x -> xh (fp16) + Wh1/Wh2 projections. Warp per row.
// ---------------------------------------------------------------------------
__global__ __launch_bounds__(256) void k_prep_x(const float2* __restrict__ x2) {
    const int row = (blockIdx.x * blockDim.x + threadIdx.x) >> 5;   // 12800 rows
    const int lane = threadIdx.x & 31;
    const float2* xr = x2 + (size_t)row * 128;
    __half2* xo = (__half2*)g_xh + (size_t)row * 128;
    float s1 = 0.f, s2 = 0.f;
#pragma unroll
    for (int q = 0; q < 4; q++) {
        const int k = lane + 32 * q;
        float2 v = xr[k];
        float2 u = ((const float2*)g_ui)[k];
        float2 w = ((const float2*)g_uj)[k];
        s1 += v.x * u.x + v.y * u.y;
        s2 += v.x * w.x + v.y * w.y;
        xo[k] = __halves2half2(__float2half_rn(v.x), __float2half_rn(v.y));
    }
#pragma unroll
    for (int o = 16; o; o >>= 1) {
        s1 += __shfl_xor_sync(0xFFFFFFFFu, s1, o);
        s2 += __shfl_xor_sync(0xFFFFFFFFu, s2, o);
    }
    if (lane == 0) {
        g_Wh1[row] = s1 + g_ci;
        g_Wh2[row] = s2 + g_cj;
    }
}

// ---------------------------------------------------------------------------
// k_bm: adjacency -> bitmask. Warp per half-row; loads batched.
// ---------------------------------------------------------------------------
__global__ __launch_bounds__(256) void k_bm(const int* __restrict__ adj) {
    const int wid = threadIdx.x >> 5;
    const int lane = threadIdx.x & 31;
    const int row = blockIdx.x * 4 + (wid >> 1);
    const int w0  = (wid & 1) * 25;
    const int* ar = adj + (size_t)row * NODES + w0 * 32 + lane;
#pragma unroll
    for (int bch = 0; bch < 3; bch++) {
        int a[10];
        const int nb = (bch == 2) ? 5 : 10;
#pragma unroll
        for (int k = 0; k < 10; k++)
            if (k < nb) a[k] = ar[(bch * 10 + k) * 32];
#pragma unroll
        for (int k = 0; k < 10; k++) {
            if (k < nb) {
                uint32_t bit = __ballot_sync(0xFFFFFFFFu, a[k] > 0);
                if (lane == 0) g_bm[row * 50 + w0 + bch * 10 + k] = bit;
            }
        }
    }
}

// ---------------------------------------------------------------------------
// k_g1mma: Wh = xh @ W16h^T (+bW), single-term; 4-stage pipeline.
// ---------------------------------------------------------------------------
__global__ __launch_bounds__(256) void k_g1mma(const float* __restrict__ bW) {
    extern __shared__ __align__(128) char dsm[];
    __shared__ float bWs[128];
    const int tid = threadIdx.x, wid = tid >> 5, lane = tid & 31;
    const int m0 = blockIdx.x * 64, n0 = blockIdx.y * 128;
    const int wm = wid >> 2, wn = wid & 3;

    if (tid < 128) bWs[tid] = bW[n0 + tid];

    const __half* Ah = g_xh + (size_t)m0 * VD;
    const __half* Bh = g_W16h + (size_t)n0 * VD;

    const uint32_t s0 = smem_u32(dsm);

    auto load_chunk = [&](int c) {
        const uint32_t st = s0 + (uint32_t)(c & 3) * STAGE_G;
        const int jt = c * KCH;
        {
            int row = tid >> 2, cc = tid & 3;
            uint32_t o = (uint32_t)(row * 80 + cc * 16);
            cp16(st + o, Ah + (size_t)row * VD + jt + cc * 8);
        }
        for (int t = tid; t < 512; t += 256) {
            int row = t >> 2, cc = t & 3;
            uint32_t o = (uint32_t)(row * 80 + cc * 16);
            cp16(st + 5120 + o, Bh + (size_t)row * VD + jt + cc * 8);
        }
        CP_COMMIT();
    };

    float acc[2][4][4];
#pragma unroll
    for (int mt = 0; mt < 2; mt++)
#pragma unroll
        for (int nt = 0; nt < 4; nt++)
#pragma unroll
            for (int q = 0; q < 4; q++) acc[mt][nt][q] = 0.f;

    const int aRow = wm * 32 + (lane & 7) + ((lane >> 3) & 1) * 8;
    const int aC16 = ((lane >> 4) & 1) * 16;
    const int bRow = wn * 32 + (lane & 7) + ((lane >> 4) & 1) * 8;
    const int bC16 = ((lane >> 3) & 1) * 16;

    load_chunk(0);
    load_chunk(1);
    load_chunk(2);

    for (int c = 0; c < NCHG; c++) {
        if      (c + 3 < NCHG) { load_chunk(c + 3); CP_WAIT3(); }
        else if (c + 2 < NCHG) CP_WAIT2();
        else if (c + 1 < NCHG) CP_WAIT1();
        else                   CP_WAIT0();
        __syncthreads();
        const uint32_t st = s0 + (uint32_t)(c & 3) * STAGE_G;
#pragma unroll
        for (int ks = 0; ks < 2; ks++) {
            const int koff = ks * 32;
            uint32_t ah[2][4], bh[2][4];
#pragma unroll
            for (int mt = 0; mt < 2; mt++) {
                uint32_t ao = st + (uint32_t)((aRow + mt * 16) * 80 + aC16 + koff);
                ldmx4(ah[mt], ao);
            }
#pragma unroll
            for (int p = 0; p < 2; p++) {
                uint32_t bo = st + 5120 +
                              (uint32_t)((bRow + p * 16) * 80 + bC16 + koff);
                ldmx4(bh[p], bo);
            }
#pragma unroll
            for (int mt = 0; mt < 2; mt++) {
#pragma unroll
                for (int nt = 0; nt < 4; nt++) {
                    const int p = nt >> 1, hf = (nt & 1) * 2;
                    mma16816(acc[mt][nt], ah[mt], bh[p][hf], bh[p][hf + 1]);
                }
            }
        }
        __syncthreads();
    }

    float* s = (float*)dsm;   // [64][129] = 33024 B (covered by SMEM_G)
#pragma unroll
    for (int mt = 0; mt < 2; mt++) {
        const int ml = wm * 32 + mt * 16 + (lane >> 2);
#pragma unroll
        for (int nt = 0; nt < 4; nt++) {
            const int nl = wn * 32 + nt * 8 + (lane & 3) * 2;
            s[ml * 129 + nl]           = acc[mt][nt][0];
            s[ml * 129 + nl + 1]       = acc[mt][nt][1];
            s[(ml + 8) * 129 + nl]     = acc[mt][nt][2];
            s[(ml + 8) * 129 + nl + 1] = acc[mt][nt][3];
        }
    }
    __syncthreads();

    const int b  = m0 / NODES;
    const int j0 = m0 % NODES;
#pragma unroll
    for (int it = 0; it < 16; it++) {
        const int f = wid * 16 + it;
        const float bw = bWs[f];
        float v0 = s[(2 * lane) * 129 + f] + bw;
        float v1 = s[(2 * lane + 1) * 129 + f] + bw;
        __half2 h = __halves2half2(__float2half_rn(v0), __float2half_rn(v1));
        size_t o = ((size_t)(b * FD + n0 + f)) * NODES + j0 + 2 * lane;
        *(__half2*)&g_WhT_hi[o] = h;
    }
}

// ---------------------------------------------------------------------------
// k_mma2f: FUSED masked-softmax + P @ Wh^T + deferred norm + ELU.
// Factored-exp: E1 = e^{Wh2-M2}, E2 = e^{0.2 Wh2} precomputed per CTA (fp16);
// per-chunk P tile needs NO MUFU (select + mul). Triple-buffered, 1 sync/chunk.
// ---------------------------------------------------------------------------
__global__ __launch_bounds__(256) void k_mma2f(float* __restrict__ out) {
    extern __shared__ __align__(128) char dsm[];
    float*    Wh2s = (float*)dsm;                 // 1600 @ 0
    float*    wh1s = Wh2s + NODES;                // 64   @ 6400
    float*    ms   = wh1s + 64;                   // 64   @ 6656
    float*    rows = ms + 64;                     // 64   @ 6912
    float*    red  = rows + 64;                   // 8    @ 7168
    uint32_t* bms  = (uint32_t*)(red + 8);        // 3200 @ 7200
    __half*   E1h  = (__half*)(dsm + 20000);      // 1600 halves
    __half*   E2h  = (__half*)(dsm + 23200);      // 1600 halves

    const int tid = threadIdx.x, wid = tid >> 5, lane = tid & 31;
    const int m0 = blockIdx.x * 64, n0 = blockIdx.y * 128, b = blockIdx.z;
    const int wm = wid >> 2, wn = wid & 3;

    const __half* Bh = g_WhT_hi + ((size_t)b * FD + n0) * NODES;

    const uint32_t s0 = smem_u32(dsm);
    const uint32_t sA = s0 + ABASE;
    const uint32_t sB = s0 + BBASE;

    auto loadB = [&](int c) {
        const uint32_t st = sB + (uint32_t)(c % 3) * 10240;
        const int jt = c * KCH;
        for (int t = tid; t < 512; t += 256) {
            int row = t >> 2, cc = t & 3;
            uint32_t o = (uint32_t)(row * 80 + cc * 16);
            cp16(st + o, Bh + (size_t)row * NODES + jt + cc * 8);
        }
        CP_COMMIT();
    };

    loadB(0);

    // ---- fill smem: Wh2 row, Wh1 tile, bitmask rows ----
    for (int j = tid; j < NODES; j += 256)
        Wh2s[j] = g_Wh2[b * NODES + j];
    if (tid < 64)
        wh1s[tid] = g_Wh1[b * NODES + m0 + tid];
    for (int t = tid; t < 64 * 50; t += 256)
        bms[t] = g_bm[m0 * 50 + t];
    __syncthreads();

    // ---- global max M2 of Wh2 (for E1 rescale) ----
    {
        float gmx = -3e38f;
        for (int j = tid; j < NODES; j += 256) gmx = fmaxf(gmx, Wh2s[j]);
#pragma unroll
        for (int o = 16; o; o >>= 1) gmx = fmaxf(gmx, __shfl_xor_sync(0xFFFFFFFFu, gmx, o));
        if (lane == 0) red[wid] = gmx;
    }
    __syncthreads();
    float M2 = red[0];
#pragma unroll
    for (int w = 1; w < 8; w++) M2 = fmaxf(M2, red[w]);

    // ---- fill E1/E2 tables + per-row masked max (both need only Wh2s/bms) --
    for (int j = tid; j < NODES; j += 256) {
        float w = Wh2s[j];
        E1h[j] = __float2half_rn(__expf(w - M2));
        E2h[j] = __float2half_rn(__expf(0.2f * w));
    }
#pragma unroll
    for (int rr = 0; rr < 8; rr++) {
        const int r = wid * 8 + rr;
        const uint32_t* bmr = &bms[r * 50];
        float mx = -3e38f;
        for (int w = 0; w < 50; w++)
            if ((bmr[w] >> lane) & 1) mx = fmaxf(mx, Wh2s[w * 32 + lane]);
#pragma unroll
        for (int o = 16; o; o >>= 1) mx = fmaxf(mx, __shfl_xor_sync(0xFFFFFFFFu, mx, o));
        if (lane == 0) {
            float em = wh1s[r] + mx;
            em = em > 0.f ? em : 0.2f * em;
            ms[r] = (mx > -1e30f) ? em : -1e9f;
        }
    }
    __syncthreads();

    float acc[2][4][4];
#pragma unroll
    for (int mt = 0; mt < 2; mt++)
#pragma unroll
        for (int nt = 0; nt < 4; nt++)
#pragma unroll
            for (int q = 0; q < 4; q++) acc[mt][nt][q] = 0.f;

    const int aRow = wm * 32 + (lane & 7) + ((lane >> 3) & 1) * 8;
    const int aC16 = ((lane >> 4) & 1) * 16;
    const int bRow = wn * 32 + (lane & 7) + ((lane >> 4) & 1) * 8;
    const int bC16 = ((lane >> 3) & 1) * 16;

    // P-tile mapping: thread -> row pr (0..63), col group pq (0..3)
    const int pr = tid >> 2, pq = tid & 3;
    const float wh1r = wh1s[pr];
    const float mr   = ms[pr];
    const uint32_t* bmp = &bms[pr * 50];
    // factored-exp row constants (3 MUFU per row, once)
    const float c1f  = __expf(wh1r - mr + M2);        // positive branch scale
    const float c2f  = __expf(0.2f * wh1r - mr);      // negative branch scale
    const float Th   = __expf(-wh1r - M2);            // sign threshold on E1
    const float mval = (mr == -1e9f) ? 1.f : 0.f;     // empty-row -> uniform
    float sacc = 0.f;

    auto computeA = [&](int c) {
        const int jt = c * KCH;
        const uint32_t word = bmp[c];
        uint32_t e1[4], e2[4], uv[4];
        *(uint4*)e1 = *(const uint4*)&E1h[jt + pq * 8];
        *(uint4*)e2 = *(const uint4*)&E2h[jt + pq * 8];
#pragma unroll
        for (int u = 0; u < 4; u++) {
            const int jj = pq * 8 + u * 2;
            float2 f1 = __half22float2(*(__half2*)&e1[u]);
            float2 f2 = __half22float2(*(__half2*)&e2[u]);
            float x0 = (f1.x > Th) ? c1f * f1.x : c2f * f2.x;
            float x1 = (f1.y > Th) ? c1f * f1.y : c2f * f2.y;
            x0 = ((word >> jj) & 1)       ? x0 : mval;
            x1 = ((word >> (jj + 1)) & 1) ? x1 : mval;
            sacc += x0 + x1;
            __half2 hh = __halves2half2(__float2half_rn(x0), __float2half_rn(x1));
            uv[u] = *(uint32_t*)&hh;
        }
        *(uint4*)(dsm + ABASE + (size_t)(c % 3) * 5120 + pr * 80 + pq * 16) =
            make_uint4(uv[0], uv[1], uv[2], uv[3]);
    };

    computeA(0);   // A(0); visible after X(0)

    for (int c = 0; c < NCH; c++) {
        if (c + 1 < NCH) { loadB(c + 1); CP_WAIT1(); }
        else             { CP_WAIT0(); }
        __syncthreads();     // X(c): A(c)+B(c) published

        const uint32_t stA = sA + (uint32_t)(c % 3) * 5120;
        const uint32_t stB = sB + (uint32_t)(c % 3) * 10240;
#pragma unroll
        for (int ks = 0; ks < 2; ks++) {
            const int koff = ks * 32;
            uint32_t ah[2][4], bh[2][4];
#pragma unroll
            for (int mt = 0; mt < 2; mt++) {
                uint32_t ao = stA + (uint32_t)((aRow + mt * 16) * 80 + aC16 + koff);
                ldmx4(ah[mt], ao);
            }
#pragma unroll
            for (int p = 0; p < 2; p++) {
                uint32_t bo = stB + (uint32_t)((bRow + p * 16) * 80 + bC16 + koff);
                ldmx4(bh[p], bo);
            }
#pragma unroll
            for (int mt = 0; mt < 2; mt++) {
#pragma unroll
                for (int nt = 0; nt < 4; nt++) {
                    const int p = nt >> 1, hf = (nt & 1) * 2;
                    mma16816(acc[mt][nt], ah[mt], bh[p][hf], bh[p][hf + 1]);
                }
            }
        }

        if (c + 1 < NCH) computeA(c + 1);   // overlaps chunk-c HMMA drain
    }

    // ---- publish row sums (reduce across the 4 pq lanes of each row) ----
    sacc += __shfl_xor_sync(0xFFFFFFFFu, sacc, 1);
    sacc += __shfl_xor_sync(0xFFFFFFFFu, sacc, 2);
    __syncthreads();
    if (pq == 0) rows[pr] = sacc;
    __syncthreads();

    // ---- epilogue: scale by 1/rowsum, ELU, store ----
#pragma unroll
    for (int mt = 0; mt < 2; mt++) {
        const int ml = wm * 32 + mt * 16 + (lane >> 2);
        const int mA = m0 + ml;
        const float ilA = 1.f / rows[ml];
        const float ilB = 1.f / rows[ml + 8];
#pragma unroll
        for (int nt = 0; nt < 4; nt++) {
            const int n = n0 + wn * 32 + nt * 8 + (lane & 3) * 2;
            float* op = out + ((size_t)(b * NODES) + mA) * FD + n;
            float d0 = acc[mt][nt][0] * ilA, d1 = acc[mt][nt][1] * ilA;
            float d2 = acc[mt][nt][2] * ilB, d3 = acc[mt][nt][3] * ilB;
            float2 v0, v1;
            v0.x = d0 > 0.f ? d0 : (__expf(d0) - 1.f);
            v0.y = d1 > 0.f ? d1 : (__expf(d1) - 1.f);
            v1.x = d2 > 0.f ? d2 : (__expf(d2) - 1.f);
            v1.y = d3 > 0.f ? d3 : (__expf(d3) - 1.f);
            *(float2*)op = v0;
            *(float2*)(op + 8 * FD) = v1;
        }
    }
}

// ---------------------------------------------------------------------------
extern "C" void kernel_launch(void* const* d_in, const int* in_sizes, int n_in,
                              void* d_out, int out_size) {
    const float* h   = (const float*)d_in[0];
    const int*   adj = (const int*)  d_in[1];
    const float* W   = (const float*)d_in[2];
    const float* bW  = (const float*)d_in[3];
    const float* ai  = (const float*)d_in[4];
    const float* bi  = (const float*)d_in[5];
    const float* aj  = (const float*)d_in[6];
    const float* bj  = (const float*)d_in[7];
    float* out = (float*)d_out;

    cudaFuncSetAttribute(k_g1mma, cudaFuncAttributeMaxDynamicSharedMemorySize, SMEM_G);
    cudaFuncSetAttribute(k_mma2f, cudaFuncAttributeMaxDynamicSharedMemorySize, SMEM_M);

    k_wprep<<<1, 256>>>(W, bW, ai, bi, aj, bj);
    k_prep_x<<<(MTOT * 32) / 256, 256>>>((const float2*)h);
    k_bm<<<NODES / 4, 256>>>(adj);
    k_g1mma<<<dim3(MTOT / 64, 2), 256, SMEM_G>>>(bW);
    dim3 gm(NODES / 64, FD / 128, BB);
    k_mma2f<<<gm, 256, SMEM_M>>>(out);
}

// round 16
// speedup vs baseline: 1.7128x; 1.0195x over previous
#include <cuda_runtime.h>
#include <cuda_fp16.h>
#include <cstdint>

#define BB      8
#define NODES   1600
#define VD      256
#define FD      256
#define MTOT    (BB * NODES)   // 12800
#define KCH     32
#define NCH     (NODES / KCH)  // 50  (k_mma2f)
#define NCHG    (VD / KCH)     // 8   (k_g1mma)
// k_g1mma: 4 stages (A hi + B hi); epilogue reuses smem as float[64][129]=33024B
#define STAGE_G 15360
#define SMEM_G  (4 * STAGE_G)           // 61440 >= 33024
// k_mma2f smem map (bytes):
// Wh2s 0..6400 | wh1s ..6656 | ms ..6912 | rows ..7168 | red ..7200 |
// bms ..20000 | E1h ..23200 | E2h ..26400 | A x3 @26400 | B x3 @41760
#define ABASE   26400
#define BBASE   (ABASE + 3 * 5120)      // 41760
#define SMEM_M  (BBASE + 3 * 10240)     // 72480

// ---------------- scratch (device globals; allocation-free) ----------------
__device__ float                 g_Wh1 [MTOT];
__device__ float                 g_Wh2 [MTOT];
__device__ float                 g_ui[VD], g_uj[VD];
__device__ float                 g_ci, g_cj;
__device__ uint32_t              g_bm[NODES * 50];
__device__ __align__(128) __half g_xh[(size_t)MTOT * VD];
__device__ __align__(128) __half g_W16h[FD * VD];
__device__ __align__(128) __half g_WhT_hi[BB * FD * NODES];

// ---------------- PTX helpers (sm_80-era only) ----------------
__device__ __forceinline__ uint32_t smem_u32(const void* p) {
    uint32_t a;
    asm("{ .reg .u64 t; cvta.to.shared.u64 t, %1; cvt.u32.u64 %0, t; }" : "=r"(a) : "l"(p));
    return a;
}
__device__ __forceinline__ void cp16(uint32_t dst, const void* src) {
    asm volatile("cp.async.cg.shared.global [%0], [%1], 16;" :: "r"(dst), "l"(src) : "memory");
}
#define CP_COMMIT() asm volatile("cp.async.commit_group;" ::: "memory")
#define CP_WAIT2()  asm volatile("cp.async.wait_group 2;" ::: "memory")
#define CP_WAIT1()  asm volatile("cp.async.wait_group 1;" ::: "memory")
#define CP_WAIT0()  asm volatile("cp.async.wait_group 0;" ::: "memory")

__device__ __forceinline__ void ldmx4(uint32_t* r, uint32_t addr) {
    asm volatile("ldmatrix.sync.aligned.m8n8.x4.shared.b16 {%0,%1,%2,%3}, [%4];"
                 : "=r"(r[0]), "=r"(r[1]), "=r"(r[2]), "=r"(r[3]) : "r"(addr));
}
__device__ __forceinline__ void mma16816(float* c, const uint32_t* a,
                                         uint32_t b0, uint32_t b1) {
    asm volatile(
        "mma.sync.aligned.m16n8k16.row.col.f32.f16.f16.f32 "
        "{%0,%1,%2,%3}, {%4,%5,%6,%7}, {%8,%9}, {%0,%1,%2,%3};"
        : "+f"(c[0]), "+f"(c[1]), "+f"(c[2]), "+f"(c[3])
        : "r"(a[0]), "r"(a[1]), "r"(a[2]), "r"(a[3]), "r"(b0), "r"(b1));
}

// ---------------------------------------------------------------------------
// k_wprep: u_i = W^T ai, u_j = W^T aj, c_i/c_j; W -> fp16 (hi only). One CTA.
// ---------------------------------------------------------------------------
__global__ __launch_bounds__(256) void k_wprep(const float* __restrict__ W,
                                               const float* __restrict__ bW,
                                               const float* __restrict__ ai,
                                               const float* __restrict__ bi,
                                               const float* __restrict__ aj,
                                               const float* __restrict__ bj) {
    __shared__ float red[16];
    const int v = threadIdx.x;
    float ui = 0.f, uj = 0.f;
    for (int f = 0; f < FD; f++) {
        float w = W[f * VD + v];
        ui += ai[f] * w;
        uj += aj[f] * w;
    }
    g_ui[v] = ui;
    g_uj[v] = uj;

    for (int t = v; t < FD * VD / 2; t += 256) {
        float2 w2 = ((const float2*)W)[t];
        *(__half2*)&g_W16h[2 * t] =
            __halves2half2(__float2half_rn(w2.x), __float2half_rn(w2.y));
    }

    float p1 = ai[v] * bW[v];
    float p2 = aj[v] * bW[v];
    const int warp = v >> 5, lane = v & 31;
#pragma unroll
    for (int o = 16; o; o >>= 1) {
        p1 += __shfl_xor_sync(0xFFFFFFFFu, p1, o);
        p2 += __shfl_xor_sync(0xFFFFFFFFu, p2, o);
    }
    if (lane == 0) { red[warp] = p1; red[8 + warp] = p2; }
    __syncthreads();
    if (v == 0) {
        float c1 = bi[0], c2 = bj[0];
        for (int w = 0; w < 8; w++) { c1 += red[w]; c2 += red[8 + w]; }
        g_ci = c1; g_cj = c2;
    }
}

// ---------------------------------------------------------------------------
// k_prep: MERGED. Blocks [0,400): adj -> bitmask (warp per half-row).
//         Blocks [400,2000): x -> xh fp16 + Wh1/Wh2 projections (warp per row).
// ---------------------------------------------------------------------------
__global__ __launch_bounds__(256) void k_prep(const float2* __restrict__ x2,
                                              const int* __restrict__ adj) {
    const int wid = threadIdx.x >> 5;
    const int lane = threadIdx.x & 31;

    if (blockIdx.x < 400) {
        // ---- bitmask part ----
        const int row = blockIdx.x * 4 + (wid >> 1);
        const int w0  = (wid & 1) * 25;
        const int* ar = adj + (size_t)row * NODES + w0 * 32 + lane;
#pragma unroll
        for (int bch = 0; bch < 3; bch++) {
            int a[10];
            const int nb = (bch == 2) ? 5 : 10;
#pragma unroll
            for (int k = 0; k < 10; k++)
                if (k < nb) a[k] = ar[(bch * 10 + k) * 32];
#pragma unroll
            for (int k = 0; k < 10; k++) {
                if (k < nb) {
                    uint32_t bit = __ballot_sync(0xFFFFFFFFu, a[k] > 0);
                    if (lane == 0) g_bm[row * 50 + w0 + bch * 10 + k] = bit;
                }
            }
        }
        return;
    }

    // ---- xh + projections part ----
    const int row = (blockIdx.x - 400) * 8 + wid;        // 1600 blocks * 8 warps
    const float2* xr = x2 + (size_t)row * 128;
    __half2* xo = (__half2*)g_xh + (size_t)row * 128;
    float s1 = 0.f, s2 = 0.f;
#pragma unroll
    for (int q = 0; q < 4; q++) {
        const int k = lane + 32 * q;
        float2 v = xr[k];
        float2 u = ((const float2*)g_ui)[k];
        float2 w = ((const float2*)g_uj)[k];
        s1 += v.x * u.x + v.y * u.y;
        s2 += v.x * w.x + v.y * w.y;
        xo[k] = __halves2half2(__float2half_rn(v.x), __float2half_rn(v.y));
    }
#pragma unroll
    for (int o = 16; o; o >>= 1) {
        s1 += __shfl_xor_sync(0xFFFFFFFFu, s1, o);
        s2 += __shfl_xor_sync(0xFFFFFFFFu, s2, o);
    }
    if (lane == 0) {
        g_Wh1[row] = s1 + g_ci;
        g_Wh2[row] = s2 + g_cj;
    }
}

// ---------------------------------------------------------------------------
// k_g1mma: Wh = xh @ W16h^T (+bW), single-term; 4-stage, ONE barrier/chunk.
// ---------------------------------------------------------------------------
__global__ __launch_bounds__(256) void k_g1mma(const float* __restrict__ bW) {
    extern __shared__ __align__(128) char dsm[];
    __shared__ float bWs[128];
    const int tid = threadIdx.x, wid = tid >> 5, lane = tid & 31;
    const int m0 = blockIdx.x * 64, n0 = blockIdx.y * 128;
    const int wm = wid >> 2, wn = wid & 3;

    if (tid < 128) bWs[tid] = bW[n0 + tid];

    const __half* Ah = g_xh + (size_t)m0 * VD;
    const __half* Bh = g_W16h + (size_t)n0 * VD;

    const uint32_t s0 = smem_u32(dsm);

    auto load_chunk = [&](int c) {
        const uint32_t st = s0 + (uint32_t)(c & 3) * STAGE_G;
        const int jt = c * KCH;
        {
            int row = tid >> 2, cc = tid & 3;
            uint32_t o = (uint32_t)(row * 80 + cc * 16);
            cp16(st + o, Ah + (size_t)row * VD + jt + cc * 8);
        }
        for (int t = tid; t < 512; t += 256) {
            int row = t >> 2, cc = t & 3;
            uint32_t o = (uint32_t)(row * 80 + cc * 16);
            cp16(st + 5120 + o, Bh + (size_t)row * VD + jt + cc * 8);
        }
        CP_COMMIT();
    };

    float acc[2][4][4];
#pragma unroll
    for (int mt = 0; mt < 2; mt++)
#pragma unroll
        for (int nt = 0; nt < 4; nt++)
#pragma unroll
            for (int q = 0; q < 4; q++) acc[mt][nt][q] = 0.f;

    const int aRow = wm * 32 + (lane & 7) + ((lane >> 3) & 1) * 8;
    const int aC16 = ((lane >> 4) & 1) * 16;
    const int bRow = wn * 32 + (lane & 7) + ((lane >> 4) & 1) * 8;
    const int bC16 = ((lane >> 3) & 1) * 16;

    load_chunk(0);
    load_chunk(1);
    load_chunk(2);

    for (int c = 0; c < NCHG; c++) {
        // tail-correct wait ladder: guarantee group c drained
        if      (c + 2 < NCHG) CP_WAIT2();
        else if (c + 1 < NCHG) CP_WAIT1();
        else                   CP_WAIT0();
        __syncthreads();   // X(c): buf c&3 published; prior readers of (c+3)&3 done

        if (c + 3 < NCHG) load_chunk(c + 3);

        const uint32_t st = s0 + (uint32_t)(c & 3) * STAGE_G;
#pragma unroll
        for (int ks = 0; ks < 2; ks++) {
            const int koff = ks * 32;
            uint32_t ah[2][4], bh[2][4];
#pragma unroll
            for (int mt = 0; mt < 2; mt++) {
                uint32_t ao = st + (uint32_t)((aRow + mt * 16) * 80 + aC16 + koff);
                ldmx4(ah[mt], ao);
            }
#pragma unroll
            for (int p = 0; p < 2; p++) {
                uint32_t bo = st + 5120 +
                              (uint32_t)((bRow + p * 16) * 80 + bC16 + koff);
                ldmx4(bh[p], bo);
            }
#pragma unroll
            for (int mt = 0; mt < 2; mt++) {
#pragma unroll
                for (int nt = 0; nt < 4; nt++) {
                    const int p = nt >> 1, hf = (nt & 1) * 2;
                    mma16816(acc[mt][nt], ah[mt], bh[p][hf], bh[p][hf + 1]);
                }
            }
        }
    }
    __syncthreads();   // all smem reads done before epilogue staging overwrites

    float* s = (float*)dsm;   // [64][129] = 33024 B (covered by SMEM_G)
#pragma unroll
    for (int mt = 0; mt < 2; mt++) {
        const int ml = wm * 32 + mt * 16 + (lane >> 2);
#pragma unroll
        for (int nt = 0; nt < 4; nt++) {
            const int nl = wn * 32 + nt * 8 + (lane & 3) * 2;
            s[ml * 129 + nl]           = acc[mt][nt][0];
            s[ml * 129 + nl + 1]       = acc[mt][nt][1];
            s[(ml + 8) * 129 + nl]     = acc[mt][nt][2];
            s[(ml + 8) * 129 + nl + 1] = acc[mt][nt][3];
        }
    }
    __syncthreads();

    const int b  = m0 / NODES;
    const int j0 = m0 % NODES;
#pragma unroll
    for (int it = 0; it < 16; it++) {
        const int f = wid * 16 + it;
        const float bw = bWs[f];
        float v0 = s[(2 * lane) * 129 + f] + bw;
        float v1 = s[(2 * lane + 1) * 129 + f] + bw;
        __half2 h = __halves2half2(__float2half_rn(v0), __float2half_rn(v1));
        size_t o = ((size_t)(b * FD + n0 + f)) * NODES + j0 + 2 * lane;
        *(__half2*)&g_WhT_hi[o] = h;
    }
}

// ---------------------------------------------------------------------------
// k_mma2f: FUSED masked-softmax + P @ Wh^T + deferred norm + ELU.
// Factored-exp tables, triple-buffered, 1 sync/chunk. (Unchanged — at HMMA
// throughput ceiling; verified correct.)
// ---------------------------------------------------------------------------
__global__ __launch_bounds__(256) void k_mma2f(float* __restrict__ out) {
    extern __shared__ __align__(128) char dsm[];
    float*    Wh2s = (float*)dsm;                 // 1600 @ 0
    float*    wh1s = Wh2s + NODES;                // 64   @ 6400
    float*    ms   = wh1s + 64;                   // 64   @ 6656
    float*    rows = ms + 64;                     // 64   @ 6912
    float*    red  = rows + 64;                   // 8    @ 7168
    uint32_t* bms  = (uint32_t*)(red + 8);        // 3200 @ 7200
    __half*   E1h  = (__half*)(dsm + 20000);      // 1600 halves
    __half*   E2h  = (__half*)(dsm + 23200);      // 1600 halves

    const int tid = threadIdx.x, wid = tid >> 5, lane = tid & 31;
    const int m0 = blockIdx.x * 64, n0 = blockIdx.y * 128, b = blockIdx.z;
    const int wm = wid >> 2, wn = wid & 3;

    const __half* Bh = g_WhT_hi + ((size_t)b * FD + n0) * NODES;

    const uint32_t s0 = smem_u32(dsm);
    const uint32_t sA = s0 + ABASE;
    const uint32_t sB = s0 + BBASE;

    auto loadB = [&](int c) {
        const uint32_t st = sB + (uint32_t)(c % 3) * 10240;
        const int jt = c * KCH;
        for (int t = tid; t < 512; t += 256) {
            int row = t >> 2, cc = t & 3;
            uint32_t o = (uint32_t)(row * 80 + cc * 16);
            cp16(st + o, Bh + (size_t)row * NODES + jt + cc * 8);
        }
        CP_COMMIT();
    };

    loadB(0);

    for (int j = tid; j < NODES; j += 256)
        Wh2s[j] = g_Wh2[b * NODES + j];
    if (tid < 64)
        wh1s[tid] = g_Wh1[b * NODES + m0 + tid];
    for (int t = tid; t < 64 * 50; t += 256)
        bms[t] = g_bm[m0 * 50 + t];
    __syncthreads();

    // ---- global max M2 of Wh2 ----
    {
        float gmx = -3e38f;
        for (int j = tid; j < NODES; j += 256) gmx = fmaxf(gmx, Wh2s[j]);
#pragma unroll
        for (int o = 16; o; o >>= 1) gmx = fmaxf(gmx, __shfl_xor_sync(0xFFFFFFFFu, gmx, o));
        if (lane == 0) red[wid] = gmx;
    }
    __syncthreads();
    float M2 = red[0];
#pragma unroll
    for (int w = 1; w < 8; w++) M2 = fmaxf(M2, red[w]);

    for (int j = tid; j < NODES; j += 256) {
        float w = Wh2s[j];
        E1h[j] = __float2half_rn(__expf(w - M2));
        E2h[j] = __float2half_rn(__expf(0.2f * w));
    }
#pragma unroll
    for (int rr = 0; rr < 8; rr++) {
        const int r = wid * 8 + rr;
        const uint32_t* bmr = &bms[r * 50];
        float mx = -3e38f;
        for (int w = 0; w < 50; w++)
            if ((bmr[w] >> lane) & 1) mx = fmaxf(mx, Wh2s[w * 32 + lane]);
#pragma unroll
        for (int o = 16; o; o >>= 1) mx = fmaxf(mx, __shfl_xor_sync(0xFFFFFFFFu, mx, o));
        if (lane == 0) {
            float em = wh1s[r] + mx;
            em = em > 0.f ? em : 0.2f * em;
            ms[r] = (mx > -1e30f) ? em : -1e9f;
        }
    }
    __syncthreads();

    float acc[2][4][4];
#pragma unroll
    for (int mt = 0; mt < 2; mt++)
#pragma unroll
        for (int nt = 0; nt < 4; nt++)
#pragma unroll
            for (int q = 0; q < 4; q++) acc[mt][nt][q] = 0.f;

    const int aRow = wm * 32 + (lane & 7) + ((lane >> 3) & 1) * 8;
    const int aC16 = ((lane >> 4) & 1) * 16;
    const int bRow = wn * 32 + (lane & 7) + ((lane >> 4) & 1) * 8;
    const int bC16 = ((lane >> 3) & 1) * 16;

    const int pr = tid >> 2, pq = tid & 3;
    const float wh1r = wh1s[pr];
    const float mr   = ms[pr];
    const uint32_t* bmp = &bms[pr * 50];
    const float c1f  = __expf(wh1r - mr + M2);
    const float c2f  = __expf(0.2f * wh1r - mr);
    const float Th   = __expf(-wh1r - M2);
    const float mval = (mr == -1e9f) ? 1.f : 0.f;
    float sacc = 0.f;

    auto computeA = [&](int c) {
        const int jt = c * KCH;
        const uint32_t word = bmp[c];
        uint32_t e1[4], e2[4], uv[4];
        *(uint4*)e1 = *(const uint4*)&E1h[jt + pq * 8];
        *(uint4*)e2 = *(const uint4*)&E2h[jt + pq * 8];
#pragma unroll
        for (int u = 0; u < 4; u++) {
            const int jj = pq * 8 + u * 2;
            float2 f1 = __half22float2(*(__half2*)&e1[u]);
            float2 f2 = __half22float2(*(__half2*)&e2[u]);
            float x0 = (f1.x > Th) ? c1f * f1.x : c2f * f2.x;
            float x1 = (f1.y > Th) ? c1f * f1.y : c2f * f2.y;
            x0 = ((word >> jj) & 1)       ? x0 : mval;
            x1 = ((word >> (jj + 1)) & 1) ? x1 : mval;
            sacc += x0 + x1;
            __half2 hh = __halves2half2(__float2half_rn(x0), __float2half_rn(x1));
            uv[u] = *(uint32_t*)&hh;
        }
        *(uint4*)(dsm + ABASE + (size_t)(c % 3) * 5120 + pr * 80 + pq * 16) =
            make_uint4(uv[0], uv[1], uv[2], uv[3]);
    };

    computeA(0);

    for (int c = 0; c < NCH; c++) {
        if (c + 1 < NCH) { loadB(c + 1); CP_WAIT1(); }
        else             { CP_WAIT0(); }
        __syncthreads();

        const uint32_t stA = sA + (uint32_t)(c % 3) * 5120;
        const uint32_t stB = sB + (uint32_t)(c % 3) * 10240;
#pragma unroll
        for (int ks = 0; ks < 2; ks++) {
            const int koff = ks * 32;
            uint32_t ah[2][4], bh[2][4];
#pragma unroll
            for (int mt = 0; mt < 2; mt++) {
                uint32_t ao = stA + (uint32_t)((aRow + mt * 16) * 80 + aC16 + koff);
                ldmx4(ah[mt], ao);
            }
#pragma unroll
            for (int p = 0; p < 2; p++) {
                uint32_t bo = stB + (uint32_t)((bRow + p * 16) * 80 + bC16 + koff);
                ldmx4(bh[p], bo);
            }
#pragma unroll
            for (int mt = 0; mt < 2; mt++) {
#pragma unroll
                for (int nt = 0; nt < 4; nt++) {
                    const int p = nt >> 1, hf = (nt & 1) * 2;
                    mma16816(acc[mt][nt], ah[mt], bh[p][hf], bh[p][hf + 1]);
                }
            }
        }

        if (c + 1 < NCH) computeA(c + 1);
    }

    sacc += __shfl_xor_sync(0xFFFFFFFFu, sacc, 1);
    sacc += __shfl_xor_sync(0xFFFFFFFFu, sacc, 2);
    __syncthreads();
    if (pq == 0) rows[pr] = sacc;
    __syncthreads();

#pragma unroll
    for (int mt = 0; mt < 2; mt++) {
        const int ml = wm * 32 + mt * 16 + (lane >> 2);
        const int mA = m0 + ml;
        const float ilA = 1.f / rows[ml];
        const float ilB = 1.f / rows[ml + 8];
#pragma unroll
        for (int nt = 0; nt < 4; nt++) {
            const int n = n0 + wn * 32 + nt * 8 + (lane & 3) * 2;
            float* op = out + ((size_t)(b * NODES) + mA) * FD + n;
            float d0 = acc[mt][nt][0] * ilA, d1 = acc[mt][nt][1] * ilA;
            float d2 = acc[mt][nt][2] * ilB, d3 = acc[mt][nt][3] * ilB;
            float2 v0, v1;
            v0.x = d0 > 0.f ? d0 : (__expf(d0) - 1.f);
            v0.y = d1 > 0.f ? d1 : (__expf(d1) - 1.f);
            v1.x = d2 > 0.f ? d2 : (__expf(d2) - 1.f);
            v1.y = d3 > 0.f ? d3 : (__expf(d3) - 1.f);
            *(float2*)op = v0;
            *(float2*)(op + 8 * FD) = v1;
        }
    }
}

// ---------------------------------------------------------------------------
extern "C" void kernel_launch(void* const* d_in, const int* in_sizes, int n_in,
                              void* d_out, int out_size) {
    const float* h   = (const float*)d_in[0];
    const int*   adj = (const int*)  d_in[1];
    const float* W   = (const float*)d_in[2];
    const float* bW  = (const float*)d_in[3];
    const float* ai  = (const float*)d_in[4];
    const float* bi  = (const float*)d_in[5];
    const float* aj  = (const float*)d_in[6];
    const float* bj  = (const float*)d_in[7];
    float* out = (float*)d_out;

    cudaFuncSetAttribute(k_g1mma, cudaFuncAttributeMaxDynamicSharedMemorySize, SMEM_G);
    cudaFuncSetAttribute(k_mma2f, cudaFuncAttributeMaxDynamicSharedMemorySize, SMEM_M);

    k_wprep<<<1, 256>>>(W, bW, ai, bi, aj, bj);
    k_prep<<<2000, 256>>>((const float2*)h, adj);
    k_g1mma<<<dim3(MTOT / 64, 2), 256, SMEM_G>>>(bW);
    dim3 gm(NODES / 64, FD / 128, BB);
    k_mma2f<<<gm, 256, SMEM_M>>>(out);
}

// round 17
// speedup vs baseline: 1.7608x; 1.0280x over previous
#include <cuda_runtime.h>
#include <cuda_fp16.h>
#include <cstdint>

#define BB      8
#define NODES   1600
#define VD      256
#define FD      256
#define MTOT    (BB * NODES)   // 12800
#define KCH     32
#define NCH     (NODES / KCH)  // 50  (k_mma2f)
#define NCHG    (VD / KCH)     // 8   (k_g1mma)
// k_g1mma: 4 stages (A hi + B hi); epilogue reuses smem as float[64][129]=33024B
#define STAGE_G 15360
#define SMEM_G  (4 * STAGE_G)           // 61440 >= 33024
// k_mma2f smem map (bytes):
// Wh2s 0..6400 | wh1s ..6656 | ms ..6912 | rows ..7168 | red ..7200 |
// bms ..20000 | E1h ..23200 | E2h ..26400 | A x3 @26400 | B x3 @41760
#define ABASE   26400
#define BBASE   (ABASE + 3 * 5120)      // 41760
#define SMEM_M  (BBASE + 3 * 10240)     // 72480 (x3 CTAs = 217.4 KB/SM)

// ---------------- scratch (device globals; allocation-free) ----------------
__device__ float                 g_Wh1 [MTOT];
__device__ float                 g_Wh2 [MTOT];
__device__ float                 g_ui[VD], g_uj[VD];
__device__ float                 g_ci, g_cj;
__device__ uint32_t              g_bm[NODES * 50];
__device__ __align__(128) __half g_xh[(size_t)MTOT * VD];
__device__ __align__(128) __half g_W16h[FD * VD];
__device__ __align__(128) __half g_WhT_hi[BB * FD * NODES];

// ---------------- PTX helpers (sm_80-era only) ----------------
__device__ __forceinline__ uint32_t smem_u32(const void* p) {
    uint32_t a;
    asm("{ .reg .u64 t; cvta.to.shared.u64 t, %1; cvt.u32.u64 %0, t; }" : "=r"(a) : "l"(p));
    return a;
}
__device__ __forceinline__ void cp16(uint32_t dst, const void* src) {
    asm volatile("cp.async.cg.shared.global [%0], [%1], 16;" :: "r"(dst), "l"(src) : "memory");
}
#define CP_COMMIT() asm volatile("cp.async.commit_group;" ::: "memory")
#define CP_WAIT2()  asm volatile("cp.async.wait_group 2;" ::: "memory")
#define CP_WAIT1()  asm volatile("cp.async.wait_group 1;" ::: "memory")
#define CP_WAIT0()  asm volatile("cp.async.wait_group 0;" ::: "memory")

__device__ __forceinline__ void ldmx4(uint32_t* r, uint32_t addr) {
    asm volatile("ldmatrix.sync.aligned.m8n8.x4.shared.b16 {%0,%1,%2,%3}, [%4];"
                 : "=r"(r[0]), "=r"(r[1]), "=r"(r[2]), "=r"(r[3]) : "r"(addr));
}
__device__ __forceinline__ void mma16816(float* c, const uint32_t* a,
                                         uint32_t b0, uint32_t b1) {
    asm volatile(
        "mma.sync.aligned.m16n8k16.row.col.f32.f16.f16.f32 "
        "{%0,%1,%2,%3}, {%4,%5,%6,%7}, {%8,%9}, {%0,%1,%2,%3};"
        : "+f"(c[0]), "+f"(c[1]), "+f"(c[2]), "+f"(c[3])
        : "r"(a[0]), "r"(a[1]), "r"(a[2]), "r"(a[3]), "r"(b0), "r"(b1));
}

// ---------------------------------------------------------------------------
// k_wprep: u_i = W^T ai, u_j = W^T aj, c_i/c_j; W -> fp16 (hi only). One CTA.
// ---------------------------------------------------------------------------
__global__ __launch_bounds__(256) void k_wprep(const float* __restrict__ W,
                                               const float* __restrict__ bW,
                                               const float* __restrict__ ai,
                                               const float* __restrict__ bi,
                                               const float* __restrict__ aj,
                                               const float* __restrict__ bj) {
    __shared__ float red[16];
    const int v = threadIdx.x;
    float ui = 0.f, uj = 0.f;
    for (int f = 0; f < FD; f++) {
        float w = W[f * VD + v];
        ui += ai[f] * w;
        uj += aj[f] * w;
    }
    g_ui[v] = ui;
    g_uj[v] = uj;

    for (int t = v; t < FD * VD / 2; t += 256) {
        float2 w2 = ((const float2*)W)[t];
        *(__half2*)&g_W16h[2 * t] =
            __halves2half2(__float2half_rn(w2.x), __float2half_rn(w2.y));
    }

    float p1 = ai[v] * bW[v];
    float p2 = aj[v] * bW[v];
    const int warp = v >> 5, lane = v & 31;
#pragma unroll
    for (int o = 16; o; o >>= 1) {
        p1 += __shfl_xor_sync(0xFFFFFFFFu, p1, o);
        p2 += __shfl_xor_sync(0xFFFFFFFFu, p2, o);
    }
    if (lane == 0) { red[warp] = p1; red[8 + warp] = p2; }
    __syncthreads();
    if (v == 0) {
        float c1 = bi[0], c2 = bj[0];
        for (int w = 0; w < 8; w++) { c1 += red[w]; c2 += red[8 + w]; }
        g_ci = c1; g_cj = c2;
    }
}

// ---------------------------------------------------------------------------
// k_prep: MERGED. Blocks [0,400): adj -> bitmask (warp per half-row).
//         Blocks [400,2000): x -> xh fp16 + Wh1/Wh2 projections (warp per row).
// ---------------------------------------------------------------------------
__global__ __launch_bounds__(256) void k_prep(const float2* __restrict__ x2,
                                              const int* __restrict__ adj) {
    const int wid = threadIdx.x >> 5;
    const int lane = threadIdx.x & 31;

    if (blockIdx.x < 400) {
        const int row = blockIdx.x * 4 + (wid >> 1);
        const int w0  = (wid & 1) * 25;
        const int* ar = adj + (size_t)row * NODES + w0 * 32 + lane;
#pragma unroll
        for (int bch = 0; bch < 3; bch++) {
            int a[10];
            const int nb = (bch == 2) ? 5 : 10;
#pragma unroll
            for (int k = 0; k < 10; k++)
                if (k < nb) a[k] = ar[(bch * 10 + k) * 32];
#pragma unroll
            for (int k = 0; k < 10; k++) {
                if (k < nb) {
                    uint32_t bit = __ballot_sync(0xFFFFFFFFu, a[k] > 0);
                    if (lane == 0) g_bm[row * 50 + w0 + bch * 10 + k] = bit;
                }
            }
        }
        return;
    }

    const int row = (blockIdx.x - 400) * 8 + wid;
    const float2* xr = x2 + (size_t)row * 128;
    __half2* xo = (__half2*)g_xh + (size_t)row * 128;
    float s1 = 0.f, s2 = 0.f;
#pragma unroll
    for (int q = 0; q < 4; q++) {
        const int k = lane + 32 * q;
        float2 v = xr[k];
        float2 u = ((const float2*)g_ui)[k];
        float2 w = ((const float2*)g_uj)[k];
        s1 += v.x * u.x + v.y * u.y;
        s2 += v.x * w.x + v.y * w.y;
        xo[k] = __halves2half2(__float2half_rn(v.x), __float2half_rn(v.y));
    }
#pragma unroll
    for (int o = 16; o; o >>= 1) {
        s1 += __shfl_xor_sync(0xFFFFFFFFu, s1, o);
        s2 += __shfl_xor_sync(0xFFFFFFFFu, s2, o);
    }
    if (lane == 0) {
        g_Wh1[row] = s1 + g_ci;
        g_Wh2[row] = s2 + g_cj;
    }
}

// ---------------------------------------------------------------------------
// k_g1mma: Wh = xh @ W16h^T (+bW), single-term; 4-stage, ONE barrier/chunk.
// ---------------------------------------------------------------------------
__global__ __launch_bounds__(256) void k_g1mma(const float* __restrict__ bW) {
    extern __shared__ __align__(128) char dsm[];
    __shared__ float bWs[128];
    const int tid = threadIdx.x, wid = tid >> 5, lane = tid & 31;
    const int m0 = blockIdx.x * 64, n0 = blockIdx.y * 128;
    const int wm = wid >> 2, wn = wid & 3;

    if (tid < 128) bWs[tid] = bW[n0 + tid];

    const __half* Ah = g_xh + (size_t)m0 * VD;
    const __half* Bh = g_W16h + (size_t)n0 * VD;

    const uint32_t s0 = smem_u32(dsm);

    auto load_chunk = [&](int c) {
        const uint32_t st = s0 + (uint32_t)(c & 3) * STAGE_G;
        const int jt = c * KCH;
        {
            int row = tid >> 2, cc = tid & 3;
            uint32_t o = (uint32_t)(row * 80 + cc * 16);
            cp16(st + o, Ah + (size_t)row * VD + jt + cc * 8);
        }
        for (int t = tid; t < 512; t += 256) {
            int row = t >> 2, cc = t & 3;
            uint32_t o = (uint32_t)(row * 80 + cc * 16);
            cp16(st + 5120 + o, Bh + (size_t)row * VD + jt + cc * 8);
        }
        CP_COMMIT();
    };

    float acc[2][4][4];
#pragma unroll
    for (int mt = 0; mt < 2; mt++)
#pragma unroll
        for (int nt = 0; nt < 4; nt++)
#pragma unroll
            for (int q = 0; q < 4; q++) acc[mt][nt][q] = 0.f;

    const int aRow = wm * 32 + (lane & 7) + ((lane >> 3) & 1) * 8;
    const int aC16 = ((lane >> 4) & 1) * 16;
    const int bRow = wn * 32 + (lane & 7) + ((lane >> 4) & 1) * 8;
    const int bC16 = ((lane >> 3) & 1) * 16;

    load_chunk(0);
    load_chunk(1);
    load_chunk(2);

    for (int c = 0; c < NCHG; c++) {
        if      (c + 2 < NCHG) CP_WAIT2();
        else if (c + 1 < NCHG) CP_WAIT1();
        else                   CP_WAIT0();
        __syncthreads();

        if (c + 3 < NCHG) load_chunk(c + 3);

        const uint32_t st = s0 + (uint32_t)(c & 3) * STAGE_G;
#pragma unroll
        for (int ks = 0; ks < 2; ks++) {
            const int koff = ks * 32;
            uint32_t ah[2][4], bh[2][4];
#pragma unroll
            for (int mt = 0; mt < 2; mt++) {
                uint32_t ao = st + (uint32_t)((aRow + mt * 16) * 80 + aC16 + koff);
                ldmx4(ah[mt], ao);
            }
#pragma unroll
            for (int p = 0; p < 2; p++) {
                uint32_t bo = st + 5120 +
                              (uint32_t)((bRow + p * 16) * 80 + bC16 + koff);
                ldmx4(bh[p], bo);
            }
#pragma unroll
            for (int mt = 0; mt < 2; mt++) {
#pragma unroll
                for (int nt = 0; nt < 4; nt++) {
                    const int p = nt >> 1, hf = (nt & 1) * 2;
                    mma16816(acc[mt][nt], ah[mt], bh[p][hf], bh[p][hf + 1]);
                }
            }
        }
    }
    __syncthreads();

    float* s = (float*)dsm;   // [64][129] = 33024 B (covered by SMEM_G)
#pragma unroll
    for (int mt = 0; mt < 2; mt++) {
        const int ml = wm * 32 + mt * 16 + (lane >> 2);
#pragma unroll
        for (int nt = 0; nt < 4; nt++) {
            const int nl = wn * 32 + nt * 8 + (lane & 3) * 2;
            s[ml * 129 + nl]           = acc[mt][nt][0];
            s[ml * 129 + nl + 1]       = acc[mt][nt][1];
            s[(ml + 8) * 129 + nl]     = acc[mt][nt][2];
            s[(ml + 8) * 129 + nl + 1] = acc[mt][nt][3];
        }
    }
    __syncthreads();

    const int b  = m0 / NODES;
    const int j0 = m0 % NODES;
#pragma unroll
    for (int it = 0; it < 16; it++) {
        const int f = wid * 16 + it;
        const float bw = bWs[f];
        float v0 = s[(2 * lane) * 129 + f] + bw;
        float v1 = s[(2 * lane + 1) * 129 + f] + bw;
        __half2 h = __halves2half2(__float2half_rn(v0), __float2half_rn(v1));
        size_t o = ((size_t)(b * FD + n0 + f)) * NODES + j0 + 2 * lane;
        *(__half2*)&g_WhT_hi[o] = h;
    }
}

// ---------------------------------------------------------------------------
// k_mma2f: FUSED masked-softmax + P @ Wh^T + deferred norm + ELU.
// __launch_bounds__(256, 3): cap regs ~85 so 3 CTAs/SM fit (was reg-limited
// to 2 at 98 regs -> occ 21%, issue 41%, all pipes idle).
// ---------------------------------------------------------------------------
__global__ __launch_bounds__(256, 3) void k_mma2f(float* __restrict__ out) {
    extern __shared__ __align__(128) char dsm[];
    float*    Wh2s = (float*)dsm;                 // 1600 @ 0
    float*    wh1s = Wh2s + NODES;                // 64   @ 6400
    float*    ms   = wh1s + 64;                   // 64   @ 6656
    float*    rows = ms + 64;                     // 64   @ 6912
    float*    red  = rows + 64;                   // 8    @ 7168
    uint32_t* bms  = (uint32_t*)(red + 8);        // 3200 @ 7200
    __half*   E1h  = (__half*)(dsm + 20000);      // 1600 halves
    __half*   E2h  = (__half*)(dsm + 23200);      // 1600 halves

    const int tid = threadIdx.x, wid = tid >> 5, lane = tid & 31;
    const int m0 = blockIdx.x * 64, n0 = blockIdx.y * 128, b = blockIdx.z;
    const int wm = wid >> 2, wn = wid & 3;

    const __half* Bh = g_WhT_hi + ((size_t)b * FD + n0) * NODES;

    const uint32_t s0 = smem_u32(dsm);
    const uint32_t sA = s0 + ABASE;
    const uint32_t sB = s0 + BBASE;

    auto loadB = [&](int c) {
        const uint32_t st = sB + (uint32_t)(c % 3) * 10240;
        const int jt = c * KCH;
        for (int t = tid; t < 512; t += 256) {
            int row = t >> 2, cc = t & 3;
            uint32_t o = (uint32_t)(row * 80 + cc * 16);
            cp16(st + o, Bh + (size_t)row * NODES + jt + cc * 8);
        }
        CP_COMMIT();
    };

    loadB(0);

    for (int j = tid; j < NODES; j += 256)
        Wh2s[j] = g_Wh2[b * NODES + j];
    if (tid < 64)
        wh1s[tid] = g_Wh1[b * NODES + m0 + tid];
    for (int t = tid; t < 64 * 50; t += 256)
        bms[t] = g_bm[m0 * 50 + t];
    __syncthreads();

    // ---- global max M2 of Wh2 ----
    {
        float gmx = -3e38f;
        for (int j = tid; j < NODES; j += 256) gmx = fmaxf(gmx, Wh2s[j]);
#pragma unroll
        for (int o = 16; o; o >>= 1) gmx = fmaxf(gmx, __shfl_xor_sync(0xFFFFFFFFu, gmx, o));
        if (lane == 0) red[wid] = gmx;
    }
    __syncthreads();
    float M2 = red[0];
#pragma unroll
    for (int w = 1; w < 8; w++) M2 = fmaxf(M2, red[w]);

    for (int j = tid; j < NODES; j += 256) {
        float w = Wh2s[j];
        E1h[j] = __float2half_rn(__expf(w - M2));
        E2h[j] = __float2half_rn(__expf(0.2f * w));
    }
#pragma unroll
    for (int rr = 0; rr < 8; rr++) {
        const int r = wid * 8 + rr;
        const uint32_t* bmr = &bms[r * 50];
        float mx = -3e38f;
        for (int w = 0; w < 50; w++)
            if ((bmr[w] >> lane) & 1) mx = fmaxf(mx, Wh2s[w * 32 + lane]);
#pragma unroll
        for (int o = 16; o; o >>= 1) mx = fmaxf(mx, __shfl_xor_sync(0xFFFFFFFFu, mx, o));
        if (lane == 0) {
            float em = wh1s[r] + mx;
            em = em > 0.f ? em : 0.2f * em;
            ms[r] = (mx > -1e30f) ? em : -1e9f;
        }
    }
    __syncthreads();

    float acc[2][4][4];
#pragma unroll
    for (int mt = 0; mt < 2; mt++)
#pragma unroll
        for (int nt = 0; nt < 4; nt++)
#pragma unroll
            for (int q = 0; q < 4; q++) acc[mt][nt][q] = 0.f;

    const int aRow = wm * 32 + (lane & 7) + ((lane >> 3) & 1) * 8;
    const int aC16 = ((lane >> 4) & 1) * 16;
    const int bRow = wn * 32 + (lane & 7) + ((lane >> 4) & 1) * 8;
    const int bC16 = ((lane >> 3) & 1) * 16;

    const int pr = tid >> 2, pq = tid & 3;
    const float wh1r = wh1s[pr];
    const float mr   = ms[pr];
    const uint32_t* bmp = &bms[pr * 50];
    const float c1f  = __expf(wh1r - mr + M2);
    const float c2f  = __expf(0.2f * wh1r - mr);
    const float Th   = __expf(-wh1r - M2);
    const float mval = (mr == -1e9f) ? 1.f : 0.f;
    float sacc = 0.f;

    auto computeA = [&](int c) {
        const int jt = c * KCH;
        const uint32_t word = bmp[c];
        uint32_t e1[4], e2[4], uv[4];
        *(uint4*)e1 = *(const uint4*)&E1h[jt + pq * 8];
        *(uint4*)e2 = *(const uint4*)&E2h[jt + pq * 8];
#pragma unroll
        for (int u = 0; u < 4; u++) {
            const int jj = pq * 8 + u * 2;
            float2 f1 = __half22float2(*(__half2*)&e1[u]);
            float2 f2 = __half22float2(*(__half2*)&e2[u]);
            float x0 = (f1.x > Th) ? c1f * f1.x : c2f * f2.x;
            float x1 = (f1.y > Th) ? c1f * f1.y : c2f * f2.y;
            x0 = ((word >> jj) & 1)       ? x0 : mval;
            x1 = ((word >> (jj + 1)) & 1) ? x1 : mval;
            sacc += x0 + x1;
            __half2 hh = __halves2half2(__float2half_rn(x0), __float2half_rn(x1));
            uv[u] = *(uint32_t*)&hh;
        }
        *(uint4*)(dsm + ABASE + (size_t)(c % 3) * 5120 + pr * 80 + pq * 16) =
            make_uint4(uv[0], uv[1], uv[2], uv[3]);
    };

    computeA(0);

    for (int c = 0; c < NCH; c++) {
        if (c + 1 < NCH) { loadB(c + 1); CP_WAIT1(); }
        else             { CP_WAIT0(); }
        __syncthreads();

        const uint32_t stA = sA + (uint32_t)(c % 3) * 5120;
        const uint32_t stB = sB + (uint32_t)(c % 3) * 10240;
#pragma unroll
        for (int ks = 0; ks < 2; ks++) {
            const int koff = ks * 32;
            uint32_t ah[2][4], bh[2][4];
#pragma unroll
            for (int mt = 0; mt < 2; mt++) {
                uint32_t ao = stA + (uint32_t)((aRow + mt * 16) * 80 + aC16 + koff);
                ldmx4(ah[mt], ao);
            }
#pragma unroll
            for (int p = 0; p < 2; p++) {
                uint32_t bo = stB + (uint32_t)((bRow + p * 16) * 80 + bC16 + koff);
                ldmx4(bh[p], bo);
            }
#pragma unroll
            for (int mt = 0; mt < 2; mt++) {
#pragma unroll
                for (int nt = 0; nt < 4; nt++) {
                    const int p = nt >> 1, hf = (nt & 1) * 2;
                    mma16816(acc[mt][nt], ah[mt], bh[p][hf], bh[p][hf + 1]);
                }
            }
        }

        if (c + 1 < NCH) computeA(c + 1);
    }

    sacc += __shfl_xor_sync(0xFFFFFFFFu, sacc, 1);
    sacc += __shfl_xor_sync(0xFFFFFFFFu, sacc, 2);
    __syncthreads();
    if (pq == 0) rows[pr] = sacc;
    __syncthreads();

#pragma unroll
    for (int mt = 0; mt < 2; mt++) {
        const int ml = wm * 32 + mt * 16 + (lane >> 2);
        const int mA = m0 + ml;
        const float ilA = 1.f / rows[ml];
        const float ilB = 1.f / rows[ml + 8];
#pragma unroll
        for (int nt = 0; nt < 4; nt++) {
            const int n = n0 + wn * 32 + nt * 8 + (lane & 3) * 2;
            float* op = out + ((size_t)(b * NODES) + mA) * FD + n;
            float d0 = acc[mt][nt][0] * ilA, d1 = acc[mt][nt][1] * ilA;
            float d2 = acc[mt][nt][2] * ilB, d3 = acc[mt][nt][3] * ilB;
            float2 v0, v1;
            v0.x = d0 > 0.f ? d0 : (__expf(d0) - 1.f);
            v0.y = d1 > 0.f ? d1 : (__expf(d1) - 1.f);
            v1.x = d2 > 0.f ? d2 : (__expf(d2) - 1.f);
            v1.y = d3 > 0.f ? d3 : (__expf(d3) - 1.f);
            *(float2*)op = v0;
            *(float2*)(op + 8 * FD) = v1;
        }
    }
}

// ---------------------------------------------------------------------------
extern "C" void kernel_launch(void* const* d_in, const int* in_sizes, int n_in,
                              void* d_out, int out_size) {
    const float* h   = (const float*)d_in[0];
    const int*   adj = (const int*)  d_in[1];
    const float* W   = (const float*)d_in[2];
    const float* bW  = (const float*)d_in[3];
    const float* ai  = (const float*)d_in[4];
    const float* bi  = (const float*)d_in[5];
    const float* aj  = (const float*)d_in[6];
    const float* bj  = (const float*)d_in[7];
    float* out = (float*)d_out;

    cudaFuncSetAttribute(k_g1mma, cudaFuncAttributeMaxDynamicSharedMemorySize, SMEM_G);
    cudaFuncSetAttribute(k_mma2f, cudaFuncAttributeMaxDynamicSharedMemorySize, SMEM_M);

    k_wprep<<<1, 256>>>(W, bW, ai, bi, aj, bj);
    k_prep<<<2000, 256>>>((const float2*)h, adj);
    k_g1mma<<<dim3(MTOT / 64, 2), 256, SMEM_G>>>(bW);
    dim3 gm(NODES / 64, FD / 128, BB);
    k_mma2f<<<gm, 256, SMEM_M>>>(out);
}